// round 6
// baseline (speedup 1.0000x reference)
#include <cuda_runtime.h>
#include <cuda_bf16.h>
#include <math.h>
#include <stdint.h>

#define T_TOKENS 8192
#define H_DIM    2048
#define I_DIM    1408
#define N_EXP    8
#define MAXTOK   8192
#define TOTROWS  (2*T_TOKENS)
#define WELEMS   (N_EXP * I_DIM * H_DIM)

// ---------------- scratch (static device globals) ----------------
__device__ __nv_bfloat16 g_xn_hi[(size_t)T_TOKENS*H_DIM];
__device__ __nv_bfloat16 g_xn_lo[(size_t)T_TOKENS*H_DIM];
__device__ __nv_bfloat16 g_h_hi[(size_t)(TOTROWS+128)*I_DIM];
__device__ __nv_bfloat16 g_h_lo[(size_t)(TOTROWS+128)*I_DIM];
__device__ float g_y[(size_t)TOTROWS*H_DIM];
__device__ int   g_cnt[N_EXP];
__device__ int   g_off[N_EXP];
__device__ int   g_tok[N_EXP*MAXTOK];
__device__ int   g_te[2*T_TOKENS];
__device__ int   g_tp[2*T_TOKENS];
__device__ float g_tw[2*T_TOKENS];
// pre-split weights (hi/lo bf16)
__device__ __nv_bfloat16 g_wg_hi[(size_t)WELEMS];
__device__ __nv_bfloat16 g_wg_lo[(size_t)WELEMS];
__device__ __nv_bfloat16 g_wu_hi[(size_t)WELEMS];
__device__ __nv_bfloat16 g_wu_lo[(size_t)WELEMS];
__device__ __nv_bfloat16 g_wd_hi[(size_t)WELEMS];
__device__ __nv_bfloat16 g_wd_lo[(size_t)WELEMS];

// ---------------- helpers ----------------
__device__ __forceinline__ uint32_t smem_u32(const void* p) {
    uint32_t a;
    asm("{ .reg .u64 t; cvta.to.shared.u64 t, %1; cvt.u32.u64 %0, t; }" : "=r"(a) : "l"(p));
    return a;
}
__device__ __forceinline__ void ldsm_x4(uint32_t* r, uint32_t addr) {
    asm volatile("ldmatrix.sync.aligned.m8n8.x4.shared.b16 {%0,%1,%2,%3}, [%4];"
        : "=r"(r[0]), "=r"(r[1]), "=r"(r[2]), "=r"(r[3]) : "r"(addr));
}
__device__ __forceinline__ void mma_bf16(float* c, const uint32_t* a, const uint32_t* b) {
    asm volatile(
        "mma.sync.aligned.m16n8k16.row.col.f32.bf16.bf16.f32 "
        "{%0,%1,%2,%3}, {%4,%5,%6,%7}, {%8,%9}, {%0,%1,%2,%3};"
        : "+f"(c[0]), "+f"(c[1]), "+f"(c[2]), "+f"(c[3])
        : "r"(a[0]), "r"(a[1]), "r"(a[2]), "r"(a[3]), "r"(b[0]), "r"(b[1]));
}
__device__ __forceinline__ void cp16(uint32_t dst, const void* src, uint32_t sz) {
    asm volatile("cp.async.cg.shared.global [%0], [%1], 16, %2;"
        :: "r"(dst), "l"(src), "r"(sz) : "memory");
}
#define CP_COMMIT() asm volatile("cp.async.commit_group;" ::: "memory")
template<int N> __device__ __forceinline__ void cp_wait() {
    asm volatile("cp.async.wait_group %0;" :: "n"(N) : "memory");
}
__device__ __forceinline__ void split_bf16(float x, __nv_bfloat16& h, __nv_bfloat16& l) {
    h = __float2bfloat16(x);
    l = __float2bfloat16(x - __bfloat162float(h));
}
__device__ __forceinline__ uint32_t pack2(__nv_bfloat16 a, __nv_bfloat16 b) {
    __nv_bfloat162 v = __halves2bfloat162(a, b);
    return *reinterpret_cast<uint32_t*>(&v);
}

// ---------------------------------------------------------------------------
__global__ void reset_kernel() {
    if (threadIdx.x < N_EXP) g_cnt[threadIdx.x] = 0;
}

// ---------------------------------------------------------------------------
__global__ __launch_bounds__(256) void split_kernel(
    const float* __restrict__ src, __nv_bfloat16* __restrict__ hi,
    __nv_bfloat16* __restrict__ lo, int n4)
{
    int i = blockIdx.x * 256 + threadIdx.x;
    if (i >= n4) return;
    float4 v = ((const float4*)src)[i];
    __nv_bfloat16 h0,l0,h1,l1,h2,l2,h3,l3;
    split_bf16(v.x,h0,l0); split_bf16(v.y,h1,l1);
    split_bf16(v.z,h2,l2); split_bf16(v.w,h3,l3);
    ((uint2*)hi)[i] = make_uint2(pack2(h0,h1), pack2(h2,h3));
    ((uint2*)lo)[i] = make_uint2(pack2(l0,l1), pack2(l2,l3));
}

// ---------------------------------------------------------------------------
__global__ __launch_bounds__(256) void router_kernel(
    const float* __restrict__ hs,
    const float* __restrict__ rmsw,
    const float* __restrict__ rw,
    float* __restrict__ out_logits)
{
    const int t   = blockIdx.x;
    const int tid = threadIdx.x;
    const float* x = hs + (size_t)t * H_DIM;

    float ss = 0.f;
    for (int i = tid; i < H_DIM; i += 256) { float v = x[i]; ss += v * v; }
    __shared__ float red[256];
    red[tid] = ss; __syncthreads();
    for (int s = 128; s > 0; s >>= 1) {
        if (tid < s) red[tid] += red[tid + s];
        __syncthreads();
    }
    __shared__ float s_scale;
    if (tid == 0) s_scale = rsqrtf(red[0] / (float)H_DIM + 1e-6f);
    __syncthreads();
    const float scale = s_scale;

    float acc[N_EXP];
#pragma unroll
    for (int e = 0; e < N_EXP; e++) acc[e] = 0.f;
    for (int i = tid; i < H_DIM; i += 256) {
        float v = x[i] * scale * rmsw[i];
        __nv_bfloat16 h, l; split_bf16(v, h, l);
        g_xn_hi[(size_t)t * H_DIM + i] = h;
        g_xn_lo[(size_t)t * H_DIM + i] = l;
#pragma unroll
        for (int e = 0; e < N_EXP; e++) acc[e] += v * rw[e * H_DIM + i];
    }

    __shared__ float slog[N_EXP];
    for (int e = 0; e < N_EXP; e++) {
        __syncthreads();
        red[tid] = acc[e]; __syncthreads();
        for (int s = 128; s > 0; s >>= 1) {
            if (tid < s) red[tid] += red[tid + s];
            __syncthreads();
        }
        if (tid == 0) slog[e] = red[0];
    }
    __syncthreads();

    if (tid == 0) {
        float l[N_EXP], m = -1e30f;
#pragma unroll
        for (int e = 0; e < N_EXP; e++) {
            l[e] = slog[e];
            out_logits[(size_t)t * N_EXP + e] = l[e];
            m = fmaxf(m, l[e]);
        }
        float p[N_EXP], s = 0.f;
#pragma unroll
        for (int e = 0; e < N_EXP; e++) { p[e] = expf(l[e] - m); s += p[e]; }
#pragma unroll
        for (int e = 0; e < N_EXP; e++) p[e] /= s;

        int a = 0;
#pragma unroll
        for (int e = 1; e < N_EXP; e++) if (p[e] > p[a]) a = e;
        int b = (a == 0) ? 1 : 0;
#pragma unroll
        for (int e = 0; e < N_EXP; e++) if (e != a && p[e] > p[b]) b = e;

        float wsum = p[a] + p[b] + 1e-20f;
        float wa = p[a] / wsum, wb = p[b] / wsum;

        int pa = atomicAdd(&g_cnt[a], 1);
        g_tok[a * MAXTOK + pa] = t;
        g_te[2*t] = a; g_tp[2*t] = pa; g_tw[2*t] = wa;
        int pb = atomicAdd(&g_cnt[b], 1);
        g_tok[b * MAXTOK + pb] = t;
        g_te[2*t+1] = b; g_tp[2*t+1] = pb; g_tw[2*t+1] = wb;
    }
}

// ---------------------------------------------------------------------------
__global__ void offsets_kernel() {
    int run = 0;
    for (int e = 0; e < N_EXP; e++) { g_off[e] = run; run += g_cnt[e]; }
}

// ---------------------------------------------------------------------------
// Pipelined bf16x3 HMMA GEMMs. Block tile 128(M) x 128(N) x 64(K), 512 threads,
// 16 warps as 4x4 (warp tile 32x32), 2-stage cp.async double buffer.
// smem rows padded to 72 bf16 (144B): conflict-free ldmatrix, 16B aligned.
#define AS 72
#define G1_STAGE (6*128*AS)            // bf16 elems per stage = 55296
#define G1_SMEM  (2*G1_STAGE*2)        // 221184 B
#define G2_STAGE (4*128*AS)            // 36864
#define G2_SMEM  (2*G2_STAGE*2)        // 147456 B

__global__ __launch_bounds__(512, 1) void gemm1_kernel()
{
    const int e  = blockIdx.z;
    const int mt = blockIdx.y;
    const int nt = blockIdx.x;
    const int cnt = g_cnt[e];
    if (mt * 128 >= cnt) return;
    const int tid = threadIdx.x;
    const int wid = tid >> 5;
    const int lane = tid & 31;

    extern __shared__ __nv_bfloat16 sm[];
    __shared__ int stok[128];

    if (tid < 128) {
        int row = mt * 128 + tid;
        stok[tid] = (row < cnt) ? g_tok[e * MAXTOK + row] : -1;
    }
    __syncthreads();

    const size_t wbase = (size_t)e * I_DIM * H_DIM + (size_t)(nt * 128) * H_DIM;
    const __nv_bfloat16* wgh = g_wg_hi + wbase;
    const __nv_bfloat16* wgl = g_wg_lo + wbase;
    const __nv_bfloat16* wuh = g_wu_hi + wbase;
    const __nv_bfloat16* wul = g_wu_lo + wbase;

    // load coordinates (512 threads)
    const int ar = tid >> 3;            // 0..63 (rows ar and ar+64)
    const int ac = (tid & 7) * 8;
    const int tok0 = stok[ar];
    const int tok1 = stok[ar + 64];
    const uint32_t v0 = tok0 >= 0 ? 16u : 0u;
    const uint32_t v1 = tok1 >= 0 ? 16u : 0u;
    const size_t as0 = (size_t)(tok0 < 0 ? 0 : tok0) * H_DIM + ac;
    const size_t as1 = (size_t)(tok1 < 0 ? 0 : tok1) * H_DIM + ac;

#define G1_LOAD(S, KK) do {                                                     \
    __nv_bfloat16* Ah = sm + (S)*G1_STAGE;                                      \
    __nv_bfloat16* Al  = Ah + 128*AS;                                           \
    __nv_bfloat16* Bgh = Ah + 2*128*AS;                                         \
    __nv_bfloat16* Bgl = Ah + 3*128*AS;                                         \
    __nv_bfloat16* Buh = Ah + 4*128*AS;                                         \
    __nv_bfloat16* Bul = Ah + 5*128*AS;                                         \
    cp16(smem_u32(Ah + ar*AS + ac),      g_xn_hi + as0 + (KK), v0);             \
    cp16(smem_u32(Al + ar*AS + ac),      g_xn_lo + as0 + (KK), v0);             \
    cp16(smem_u32(Ah + (ar+64)*AS + ac), g_xn_hi + as1 + (KK), v1);             \
    cp16(smem_u32(Al + (ar+64)*AS + ac), g_xn_lo + as1 + (KK), v1);             \
    size_t b0 = (size_t)ar * H_DIM + (KK) + ac;                                 \
    size_t b1 = (size_t)(ar+64) * H_DIM + (KK) + ac;                            \
    cp16(smem_u32(Bgh + ar*AS + ac),      wgh + b0, 16u);                       \
    cp16(smem_u32(Bgl + ar*AS + ac),      wgl + b0, 16u);                       \
    cp16(smem_u32(Buh + ar*AS + ac),      wuh + b0, 16u);                       \
    cp16(smem_u32(Bul + ar*AS + ac),      wul + b0, 16u);                       \
    cp16(smem_u32(Bgh + (ar+64)*AS + ac), wgh + b1, 16u);                       \
    cp16(smem_u32(Bgl + (ar+64)*AS + ac), wgl + b1, 16u);                       \
    cp16(smem_u32(Buh + (ar+64)*AS + ac), wuh + b1, 16u);                       \
    cp16(smem_u32(Bul + (ar+64)*AS + ac), wul + b1, 16u);                       \
} while (0)

    float cg[2][4][4], cu[2][4][4];
#pragma unroll
    for (int i = 0; i < 2; i++)
#pragma unroll
        for (int j = 0; j < 4; j++)
#pragma unroll
            for (int k = 0; k < 4; k++) { cg[i][j][k] = 0.f; cu[i][j][k] = 0.f; }

    const int wm = wid >> 2;          // 0..3
    const int wn = wid & 3;           // 0..3
    const int lr = lane & 15;
    const int lc = (lane >> 4) * 8;

    G1_LOAD(0, 0);
    CP_COMMIT();

    const int KT = H_DIM / 64;
    for (int kt = 0; kt < KT; kt++) {
        const int s = kt & 1;
        if (kt + 1 < KT) {
            G1_LOAD(s ^ 1, (kt + 1) * 64);
            CP_COMMIT();
            cp_wait<1>();
        } else {
            cp_wait<0>();
        }
        __syncthreads();

        const __nv_bfloat16* Ah  = sm + s*G1_STAGE;
        const __nv_bfloat16* Al  = Ah + 128*AS;
        const __nv_bfloat16* Bgh = Ah + 2*128*AS;
        const __nv_bfloat16* Bgl = Ah + 3*128*AS;
        const __nv_bfloat16* Buh = Ah + 4*128*AS;
        const __nv_bfloat16* Bul = Ah + 5*128*AS;

#pragma unroll
        for (int ks = 0; ks < 4; ks++) {
            uint32_t ah[2][4], al[2][4];
#pragma unroll
            for (int mf = 0; mf < 2; mf++) {
                int so = (wm*32 + mf*16 + lr) * AS + ks*16 + lc;
                ldsm_x4(ah[mf], smem_u32(Ah + so));
                ldsm_x4(al[mf], smem_u32(Al + so));
            }
            uint32_t bgh[2][4], bgl[2][4], buh[2][4], bul[2][4];
#pragma unroll
            for (int n2 = 0; n2 < 2; n2++) {
                int so = (wn*32 + n2*16 + lr) * AS + ks*16 + lc;
                ldsm_x4(bgh[n2], smem_u32(Bgh + so));
                ldsm_x4(bgl[n2], smem_u32(Bgl + so));
                ldsm_x4(buh[n2], smem_u32(Buh + so));
                ldsm_x4(bul[n2], smem_u32(Bul + so));
            }
#pragma unroll
            for (int mf = 0; mf < 2; mf++)
#pragma unroll
            for (int nf = 0; nf < 4; nf++) {
                int n2 = nf >> 1, nh = nf & 1;
                uint32_t bG [2] = { bgh[n2][nh], bgh[n2][nh+2] };
                uint32_t bGl[2] = { bgl[n2][nh], bgl[n2][nh+2] };
                uint32_t bU [2] = { buh[n2][nh], buh[n2][nh+2] };
                uint32_t bUl[2] = { bul[n2][nh], bul[n2][nh+2] };
                // interleave cg/cu chains for ILP
                mma_bf16(cg[mf][nf], ah[mf], bG);
                mma_bf16(cu[mf][nf], ah[mf], bU);
                mma_bf16(cg[mf][nf], al[mf], bG);
                mma_bf16(cu[mf][nf], al[mf], bU);
                mma_bf16(cg[mf][nf], ah[mf], bGl);
                mma_bf16(cu[mf][nf], ah[mf], bUl);
            }
        }
        __syncthreads();
    }
#undef G1_LOAD

    // epilogue: h = silu(g) * u, split-bf16 packed stores
    const int off = g_off[e];
#pragma unroll
    for (int mf = 0; mf < 2; mf++)
#pragma unroll
    for (int nf = 0; nf < 4; nf++) {
        int col = nt*128 + wn*32 + nf*8 + (lane & 3)*2;
#pragma unroll
        for (int half = 0; half < 2; half++) {
            int row = mt*128 + wm*32 + mf*16 + (lane >> 2) + half*8;
            if (row < cnt) {
                float g0 = cg[mf][nf][half*2],   g1 = cg[mf][nf][half*2+1];
                float u0 = cu[mf][nf][half*2],   u1 = cu[mf][nf][half*2+1];
                float h0 = (g0 / (1.f + expf(-g0))) * u0;
                float h1 = (g1 / (1.f + expf(-g1))) * u1;
                __nv_bfloat16 a0,b0,a1,b1;
                split_bf16(h0, a0, b0); split_bf16(h1, a1, b1);
                size_t base = (size_t)(off + row) * I_DIM + col;
                *(uint32_t*)(g_h_hi + base) = pack2(a0, a1);
                *(uint32_t*)(g_h_lo + base) = pack2(b0, b1);
            }
        }
    }
}

// ---------------------------------------------------------------------------
__global__ __launch_bounds__(512, 1) void gemm2_kernel()
{
    const int e  = blockIdx.z;
    const int mt = blockIdx.y;
    const int nt = blockIdx.x;
    const int cnt = g_cnt[e];
    if (mt * 128 >= cnt) return;
    const int tid = threadIdx.x;
    const int wid = tid >> 5;
    const int lane = tid & 31;
    const int off = g_off[e];

    extern __shared__ __nv_bfloat16 sm[];

    const size_t wbase = (size_t)e * H_DIM * I_DIM + (size_t)(nt * 128) * I_DIM;
    const __nv_bfloat16* wdh = g_wd_hi + wbase;
    const __nv_bfloat16* wdl = g_wd_lo + wbase;

    const int ar = tid >> 3;
    const int ac = (tid & 7) * 8;
    const size_t as0 = (size_t)(off + mt*128 + ar) * I_DIM + ac;
    const size_t as1 = (size_t)(off + mt*128 + ar + 64) * I_DIM + ac;

#define G2_LOAD(S, KK) do {                                                     \
    __nv_bfloat16* Ah = sm + (S)*G2_STAGE;                                      \
    __nv_bfloat16* Al = Ah + 128*AS;                                            \
    __nv_bfloat16* Bh = Ah + 2*128*AS;                                          \
    __nv_bfloat16* Bl = Ah + 3*128*AS;                                          \
    cp16(smem_u32(Ah + ar*AS + ac),      g_h_hi + as0 + (KK), 16u);             \
    cp16(smem_u32(Al + ar*AS + ac),      g_h_lo + as0 + (KK), 16u);             \
    cp16(smem_u32(Ah + (ar+64)*AS + ac), g_h_hi + as1 + (KK), 16u);             \
    cp16(smem_u32(Al + (ar+64)*AS + ac), g_h_lo + as1 + (KK), 16u);             \
    size_t b0 = (size_t)ar * I_DIM + (KK) + ac;                                 \
    size_t b1 = (size_t)(ar+64) * I_DIM + (KK) + ac;                            \
    cp16(smem_u32(Bh + ar*AS + ac),      wdh + b0, 16u);                        \
    cp16(smem_u32(Bl + ar*AS + ac),      wdl + b0, 16u);                        \
    cp16(smem_u32(Bh + (ar+64)*AS + ac), wdh + b1, 16u);                        \
    cp16(smem_u32(Bl + (ar+64)*AS + ac), wdl + b1, 16u);                        \
} while (0)

    float cc[2][4][4];
#pragma unroll
    for (int i = 0; i < 2; i++)
#pragma unroll
        for (int j = 0; j < 4; j++)
#pragma unroll
            for (int k = 0; k < 4; k++) cc[i][j][k] = 0.f;

    const int wm = wid >> 2;
    const int wn = wid & 3;
    const int lr = lane & 15;
    const int lc = (lane >> 4) * 8;

    G2_LOAD(0, 0);
    CP_COMMIT();

    const int KT = I_DIM / 64;
    for (int kt = 0; kt < KT; kt++) {
        const int s = kt & 1;
        if (kt + 1 < KT) {
            G2_LOAD(s ^ 1, (kt + 1) * 64);
            CP_COMMIT();
            cp_wait<1>();
        } else {
            cp_wait<0>();
        }
        __syncthreads();

        const __nv_bfloat16* Ah = sm + s*G2_STAGE;
        const __nv_bfloat16* Al = Ah + 128*AS;
        const __nv_bfloat16* Bh = Ah + 2*128*AS;
        const __nv_bfloat16* Bl = Ah + 3*128*AS;

#pragma unroll
        for (int ks = 0; ks < 4; ks++) {
            uint32_t ah[2][4], al[2][4];
#pragma unroll
            for (int mf = 0; mf < 2; mf++) {
                int so = (wm*32 + mf*16 + lr) * AS + ks*16 + lc;
                ldsm_x4(ah[mf], smem_u32(Ah + so));
                ldsm_x4(al[mf], smem_u32(Al + so));
            }
            uint32_t bh[2][4], bl[2][4];
#pragma unroll
            for (int n2 = 0; n2 < 2; n2++) {
                int so = (wn*32 + n2*16 + lr) * AS + ks*16 + lc;
                ldsm_x4(bh[n2], smem_u32(Bh + so));
                ldsm_x4(bl[n2], smem_u32(Bl + so));
            }
#pragma unroll
            for (int mf = 0; mf < 2; mf++)
#pragma unroll
            for (int nf = 0; nf < 4; nf++) {
                int n2 = nf >> 1, nh = nf & 1;
                uint32_t bH[2] = { bh[n2][nh], bh[n2][nh+2] };
                uint32_t bL[2] = { bl[n2][nh], bl[n2][nh+2] };
                mma_bf16(cc[mf][nf], ah[mf], bH);
                mma_bf16(cc[mf][nf], al[mf], bH);
                mma_bf16(cc[mf][nf], ah[mf], bL);
            }
        }
        __syncthreads();
    }
#undef G2_LOAD

    // epilogue: store unscaled y rows (fp32)
#pragma unroll
    for (int mf = 0; mf < 2; mf++)
#pragma unroll
    for (int nf = 0; nf < 4; nf++) {
        int col = nt*128 + wn*32 + nf*8 + (lane & 3)*2;
#pragma unroll
        for (int half = 0; half < 2; half++) {
            int row = mt*128 + wm*32 + mf*16 + (lane >> 2) + half*8;
            if (row < cnt) {
                float2 v = make_float2(cc[mf][nf][half*2], cc[mf][nf][half*2+1]);
                *(float2*)(g_y + (size_t)(off + row) * H_DIM + col) = v;
            }
        }
    }
}

// ---------------------------------------------------------------------------
__global__ __launch_bounds__(256) void combine_kernel(float* __restrict__ out)
{
    const int t = blockIdx.x;
    const int tid = threadIdx.x;
    const int e0 = g_te[2*t],   p0 = g_tp[2*t];
    const int e1 = g_te[2*t+1], p1 = g_tp[2*t+1];
    const float w0 = g_tw[2*t], w1 = g_tw[2*t+1];
    const float* y0 = g_y + (size_t)(g_off[e0] + p0) * H_DIM;
    const float* y1 = g_y + (size_t)(g_off[e1] + p1) * H_DIM;
    float* o = out + (size_t)t * H_DIM;
#pragma unroll
    for (int it = 0; it < 2; it++) {
        int i = (tid + it * 256) * 4;
        float4 a = *(const float4*)(y0 + i);
        float4 b = *(const float4*)(y1 + i);
        float4 r;
        r.x = w0 * a.x + w1 * b.x;
        r.y = w0 * a.y + w1 * b.y;
        r.z = w0 * a.z + w1 * b.z;
        r.w = w0 * a.w + w1 * b.w;
        *(float4*)(o + i) = r;
    }
}

// ---------------------------------------------------------------------------
extern "C" void kernel_launch(void* const* d_in, const int* in_sizes, int n_in,
                              void* d_out, int out_size)
{
    const float* hs   = (const float*)d_in[0];
    const float* rmsw = (const float*)d_in[1];
    const float* rw   = (const float*)d_in[2];
    const float* wg   = (const float*)d_in[3];
    const float* wu   = (const float*)d_in[4];
    const float* wd   = (const float*)d_in[5];

    float* out        = (float*)d_out;
    float* out_logits = (float*)d_out + (size_t)T_TOKENS * H_DIM;

    cudaFuncSetAttribute(gemm1_kernel, cudaFuncAttributeMaxDynamicSharedMemorySize, G1_SMEM);
    cudaFuncSetAttribute(gemm2_kernel, cudaFuncAttributeMaxDynamicSharedMemorySize, G2_SMEM);

    // pre-split weights
    {
        __nv_bfloat16 *wgh, *wgl, *wuh, *wul, *wdh, *wdl;
        cudaGetSymbolAddress((void**)&wgh, g_wg_hi);
        cudaGetSymbolAddress((void**)&wgl, g_wg_lo);
        cudaGetSymbolAddress((void**)&wuh, g_wu_hi);
        cudaGetSymbolAddress((void**)&wul, g_wu_lo);
        cudaGetSymbolAddress((void**)&wdh, g_wd_hi);
        cudaGetSymbolAddress((void**)&wdl, g_wd_lo);
        int n4 = WELEMS / 4;
        int blocks = (n4 + 255) / 256;
        split_kernel<<<blocks, 256>>>(wg, wgh, wgl, n4);
        split_kernel<<<blocks, 256>>>(wu, wuh, wul, n4);
        split_kernel<<<blocks, 256>>>(wd, wdh, wdl, n4);
    }

    reset_kernel<<<1, 32>>>();
    router_kernel<<<T_TOKENS, 256>>>(hs, rmsw, rw, out_logits);
    offsets_kernel<<<1, 1>>>();

    dim3 g1(I_DIM / 128, T_TOKENS / 128, N_EXP);   // 11 x 64 x 8
    gemm1_kernel<<<g1, 512, G1_SMEM>>>();

    dim3 g2(H_DIM / 128, T_TOKENS / 128, N_EXP);   // 16 x 64 x 8
    gemm2_kernel<<<g2, 512, G2_SMEM>>>();

    combine_kernel<<<T_TOKENS, 256>>>(out);
}

// round 7
// speedup vs baseline: 1.3441x; 1.3441x over previous
#include <cuda_runtime.h>
#include <cuda_fp16.h>
#include <math.h>
#include <stdint.h>

#define T_TOKENS 8192
#define H_DIM    2048
#define I_DIM    1408
#define N_EXP    8
#define MAXTOK   8192
#define TOTROWS  (2*T_TOKENS)
#define WELEMS   (N_EXP * I_DIM * H_DIM)

// ---------------- scratch (static device globals) ----------------
__device__ __half g_xn[(size_t)T_TOKENS*H_DIM];
__device__ __half g_h [(size_t)(TOTROWS+128)*I_DIM];
__device__ float  g_y [(size_t)TOTROWS*H_DIM];
__device__ int    g_cnt[N_EXP];
__device__ int    g_off[N_EXP];
__device__ int    g_tok[N_EXP*MAXTOK];
__device__ int    g_te[2*T_TOKENS];
__device__ int    g_tp[2*T_TOKENS];
__device__ float  g_tw[2*T_TOKENS];
// pre-split weights (hi/lo fp16)
__device__ __half g_wg_hi[(size_t)WELEMS];
__device__ __half g_wg_lo[(size_t)WELEMS];
__device__ __half g_wu_hi[(size_t)WELEMS];
__device__ __half g_wu_lo[(size_t)WELEMS];
__device__ __half g_wd_hi[(size_t)WELEMS];
__device__ __half g_wd_lo[(size_t)WELEMS];

// ---------------- helpers ----------------
__device__ __forceinline__ uint32_t smem_u32(const void* p) {
    uint32_t a;
    asm("{ .reg .u64 t; cvta.to.shared.u64 t, %1; cvt.u32.u64 %0, t; }" : "=r"(a) : "l"(p));
    return a;
}
__device__ __forceinline__ void ldsm_x4(uint32_t* r, uint32_t addr) {
    asm volatile("ldmatrix.sync.aligned.m8n8.x4.shared.b16 {%0,%1,%2,%3}, [%4];"
        : "=r"(r[0]), "=r"(r[1]), "=r"(r[2]), "=r"(r[3]) : "r"(addr));
}
__device__ __forceinline__ void mma_fp16(float* c, const uint32_t* a, const uint32_t* b) {
    asm volatile(
        "mma.sync.aligned.m16n8k16.row.col.f32.f16.f16.f32 "
        "{%0,%1,%2,%3}, {%4,%5,%6,%7}, {%8,%9}, {%0,%1,%2,%3};"
        : "+f"(c[0]), "+f"(c[1]), "+f"(c[2]), "+f"(c[3])
        : "r"(a[0]), "r"(a[1]), "r"(a[2]), "r"(a[3]), "r"(b[0]), "r"(b[1]));
}
__device__ __forceinline__ void split_fp16(float x, __half& h, __half& l) {
    h = __float2half_rn(x);
    l = __float2half_rn(x - __half2float(h));
}
__device__ __forceinline__ uint32_t packh2(__half a, __half b) {
    __half2 v = __halves2half2(a, b);
    return *reinterpret_cast<uint32_t*>(&v);
}

// ---------------------------------------------------------------------------
__global__ void reset_kernel() {
    if (threadIdx.x < N_EXP) g_cnt[threadIdx.x] = 0;
}

// ---------------------------------------------------------------------------
// pre-split weights: fp32 -> (hi, lo) fp16
__global__ __launch_bounds__(256) void split_kernel(
    const float* __restrict__ src, __half* __restrict__ hi,
    __half* __restrict__ lo, int n4)
{
    int i = blockIdx.x * 256 + threadIdx.x;
    if (i >= n4) return;
    float4 v = ((const float4*)src)[i];
    __half h0,l0,h1,l1,h2,l2,h3,l3;
    split_fp16(v.x,h0,l0); split_fp16(v.y,h1,l1);
    split_fp16(v.z,h2,l2); split_fp16(v.w,h3,l3);
    ((uint2*)hi)[i] = make_uint2(packh2(h0,h1), packh2(h2,h3));
    ((uint2*)lo)[i] = make_uint2(packh2(l0,l1), packh2(l2,l3));
}

// ---------------------------------------------------------------------------
__global__ __launch_bounds__(256) void router_kernel(
    const float* __restrict__ hs,
    const float* __restrict__ rmsw,
    const float* __restrict__ rw,
    float* __restrict__ out_logits)
{
    const int t   = blockIdx.x;
    const int tid = threadIdx.x;
    const float* x = hs + (size_t)t * H_DIM;

    float ss = 0.f;
    for (int i = tid; i < H_DIM; i += 256) { float v = x[i]; ss += v * v; }
    __shared__ float red[256];
    red[tid] = ss; __syncthreads();
    for (int s = 128; s > 0; s >>= 1) {
        if (tid < s) red[tid] += red[tid + s];
        __syncthreads();
    }
    __shared__ float s_scale;
    if (tid == 0) s_scale = rsqrtf(red[0] / (float)H_DIM + 1e-6f);
    __syncthreads();
    const float scale = s_scale;

    float acc[N_EXP];
#pragma unroll
    for (int e = 0; e < N_EXP; e++) acc[e] = 0.f;
    for (int i = tid; i < H_DIM; i += 256) {
        float v = x[i] * scale * rmsw[i];
        g_xn[(size_t)t * H_DIM + i] = __float2half_rn(v);
#pragma unroll
        for (int e = 0; e < N_EXP; e++) acc[e] += v * rw[e * H_DIM + i];
    }

    __shared__ float slog[N_EXP];
    for (int e = 0; e < N_EXP; e++) {
        __syncthreads();
        red[tid] = acc[e]; __syncthreads();
        for (int s = 128; s > 0; s >>= 1) {
            if (tid < s) red[tid] += red[tid + s];
            __syncthreads();
        }
        if (tid == 0) slog[e] = red[0];
    }
    __syncthreads();

    if (tid == 0) {
        float l[N_EXP], m = -1e30f;
#pragma unroll
        for (int e = 0; e < N_EXP; e++) {
            l[e] = slog[e];
            out_logits[(size_t)t * N_EXP + e] = l[e];
            m = fmaxf(m, l[e]);
        }
        float p[N_EXP], s = 0.f;
#pragma unroll
        for (int e = 0; e < N_EXP; e++) { p[e] = expf(l[e] - m); s += p[e]; }
#pragma unroll
        for (int e = 0; e < N_EXP; e++) p[e] /= s;

        int a = 0;
#pragma unroll
        for (int e = 1; e < N_EXP; e++) if (p[e] > p[a]) a = e;
        int b = (a == 0) ? 1 : 0;
#pragma unroll
        for (int e = 0; e < N_EXP; e++) if (e != a && p[e] > p[b]) b = e;

        float wsum = p[a] + p[b] + 1e-20f;
        float wa = p[a] / wsum, wb = p[b] / wsum;

        int pa = atomicAdd(&g_cnt[a], 1);
        g_tok[a * MAXTOK + pa] = t;
        g_te[2*t] = a; g_tp[2*t] = pa; g_tw[2*t] = wa;
        int pb = atomicAdd(&g_cnt[b], 1);
        g_tok[b * MAXTOK + pb] = t;
        g_te[2*t+1] = b; g_tp[2*t+1] = pb; g_tw[2*t+1] = wb;
    }
}

// ---------------------------------------------------------------------------
__global__ void offsets_kernel() {
    int run = 0;
    for (int e = 0; e < N_EXP; e++) { g_off[e] = run; run += g_cnt[e]; }
}

// ---------------------------------------------------------------------------
// Tiled fp16x2 HMMA GEMMs (round-3 structure, 2-term split).
// Block tile 128(M) x 64(N), K-tile 64, 256 threads, warp grid 4x2 (warp 32x32).
// A: single fp16. B: fp16 hi + lo. D = A*Bh + A*Bl.
// smem rows padded to 72 halves (144B): conflict-free ldmatrix, 16B aligned.
#define AS 72
#define G1_SMEM ((128*AS + 4*64*AS) * 2)   // 55296 B
#define G2_SMEM ((128*AS + 2*64*AS) * 2)   // 36864 B

__global__ __launch_bounds__(256) void gemm1_kernel()
{
    const int e  = blockIdx.z;
    const int mt = blockIdx.y;
    const int nt = blockIdx.x;
    const int cnt = g_cnt[e];
    if (mt * 128 >= cnt) return;
    const int tid = threadIdx.x;
    const int wid = tid >> 5;
    const int lane = tid & 31;

    extern __shared__ __half sm[];
    __shared__ int stok[128];
    __half* Ah  = sm;
    __half* Bgh = sm + 128*AS;
    __half* Bgl = Bgh + 64*AS;
    __half* Buh = Bgl + 64*AS;
    __half* Bul = Buh + 64*AS;

    if (tid < 128) {
        int row = mt * 128 + tid;
        stok[tid] = (row < cnt) ? g_tok[e * MAXTOK + row] : -1;
    }

    const size_t wbase = (size_t)e * I_DIM * H_DIM + (size_t)(nt * 64) * H_DIM;
    const __half* wgh = g_wg_hi + wbase;
    const __half* wgl = g_wg_lo + wbase;
    const __half* wuh = g_wu_hi + wbase;
    const __half* wul = g_wu_lo + wbase;

    float cg[2][4][4], cu[2][4][4];
#pragma unroll
    for (int i = 0; i < 2; i++)
#pragma unroll
        for (int j = 0; j < 4; j++)
#pragma unroll
            for (int k = 0; k < 4; k++) { cg[i][j][k] = 0.f; cu[i][j][k] = 0.f; }

    const int wm = wid >> 1;          // 0..3
    const int wn = wid & 1;           // 0..1
    const int lr = lane & 15;
    const int lc = (lane >> 4) * 8;

    for (int kk = 0; kk < H_DIM; kk += 64) {
        __syncthreads();
        // A: 128 rows x 64 fp16, gathered by token
#pragma unroll
        for (int p = 0; p < 4; p++) {
            int q = tid + p * 256;
            int r = q >> 3, c8 = (q & 7) * 8;
            int tok = stok[r];
            uint4 vh = make_uint4(0,0,0,0);
            if (tok >= 0) vh = *(const uint4*)(g_xn + (size_t)tok * H_DIM + kk + c8);
            *(uint4*)(Ah + r * AS + c8) = vh;
        }
        // B: 64 rows x 64 fp16 per array (gate hi/lo, up hi/lo)
#pragma unroll
        for (int p = 0; p < 2; p++) {
            int q = tid + p * 256;
            int n = q >> 3, c8 = (q & 7) * 8;
            size_t gi = (size_t)n * H_DIM + kk + c8;
            int so = n * AS + c8;
            *(uint4*)(Bgh + so) = *(const uint4*)(wgh + gi);
            *(uint4*)(Bgl + so) = *(const uint4*)(wgl + gi);
            *(uint4*)(Buh + so) = *(const uint4*)(wuh + gi);
            *(uint4*)(Bul + so) = *(const uint4*)(wul + gi);
        }
        __syncthreads();

#pragma unroll
        for (int ks = 0; ks < 4; ks++) {
            uint32_t ah[2][4];
#pragma unroll
            for (int mf = 0; mf < 2; mf++) {
                int so = (wm*32 + mf*16 + lr) * AS + ks*16 + lc;
                ldsm_x4(ah[mf], smem_u32(Ah + so));
            }
            uint32_t bgh[2][4], bgl[2][4], buh[2][4], bul[2][4];
#pragma unroll
            for (int n2 = 0; n2 < 2; n2++) {
                int so = (wn*32 + n2*16 + lr) * AS + ks*16 + lc;
                ldsm_x4(bgh[n2], smem_u32(Bgh + so));
                ldsm_x4(bgl[n2], smem_u32(Bgl + so));
                ldsm_x4(buh[n2], smem_u32(Buh + so));
                ldsm_x4(bul[n2], smem_u32(Bul + so));
            }
#pragma unroll
            for (int mf = 0; mf < 2; mf++)
#pragma unroll
            for (int nf = 0; nf < 4; nf++) {
                int n2 = nf >> 1, nh = nf & 1;
                uint32_t bG [2] = { bgh[n2][nh], bgh[n2][nh+2] };
                uint32_t bGl[2] = { bgl[n2][nh], bgl[n2][nh+2] };
                uint32_t bU [2] = { buh[n2][nh], buh[n2][nh+2] };
                uint32_t bUl[2] = { bul[n2][nh], bul[n2][nh+2] };
                mma_fp16(cg[mf][nf], ah[mf], bG);
                mma_fp16(cu[mf][nf], ah[mf], bU);
                mma_fp16(cg[mf][nf], ah[mf], bGl);
                mma_fp16(cu[mf][nf], ah[mf], bUl);
            }
        }
    }

    // epilogue: h = silu(g) * u, single fp16 store
    const int off = g_off[e];
#pragma unroll
    for (int mf = 0; mf < 2; mf++)
#pragma unroll
    for (int nf = 0; nf < 4; nf++) {
        int col = nt*64 + wn*32 + nf*8 + (lane & 3)*2;
#pragma unroll
        for (int half = 0; half < 2; half++) {
            int row = mt*128 + wm*32 + mf*16 + (lane >> 2) + half*8;
            if (row < cnt) {
                float g0 = cg[mf][nf][half*2],   g1 = cg[mf][nf][half*2+1];
                float u0 = cu[mf][nf][half*2],   u1 = cu[mf][nf][half*2+1];
                float h0 = (g0 / (1.f + expf(-g0))) * u0;
                float h1 = (g1 / (1.f + expf(-g1))) * u1;
                size_t base = (size_t)(off + row) * I_DIM + col;
                *(uint32_t*)(g_h + base) = packh2(__float2half_rn(h0), __float2half_rn(h1));
            }
        }
    }
}

// ---------------------------------------------------------------------------
__global__ __launch_bounds__(256) void gemm2_kernel()
{
    const int e  = blockIdx.z;
    const int mt = blockIdx.y;
    const int nt = blockIdx.x;
    const int cnt = g_cnt[e];
    if (mt * 128 >= cnt) return;
    const int tid = threadIdx.x;
    const int wid = tid >> 5;
    const int lane = tid & 31;
    const int off = g_off[e];

    extern __shared__ __half sm[];
    __half* Ah = sm;
    __half* Bh = sm + 128*AS;
    __half* Bl = Bh + 64*AS;

    const size_t wbase = (size_t)e * H_DIM * I_DIM + (size_t)(nt * 64) * I_DIM;
    const __half* wdh = g_wd_hi + wbase;
    const __half* wdl = g_wd_lo + wbase;

    float cc[2][4][4];
#pragma unroll
    for (int i = 0; i < 2; i++)
#pragma unroll
        for (int j = 0; j < 4; j++)
#pragma unroll
            for (int k = 0; k < 4; k++) cc[i][j][k] = 0.f;

    const int wm = wid >> 1;
    const int wn = wid & 1;
    const int lr = lane & 15;
    const int lc = (lane >> 4) * 8;

    for (int kk = 0; kk < I_DIM; kk += 64) {
        __syncthreads();
#pragma unroll
        for (int p = 0; p < 4; p++) {
            int q = tid + p * 256;
            int r = q >> 3, c8 = (q & 7) * 8;
            uint4 vh = *(const uint4*)(g_h + (size_t)(off + mt*128 + r) * I_DIM + kk + c8);
            *(uint4*)(Ah + r * AS + c8) = vh;
        }
#pragma unroll
        for (int p = 0; p < 2; p++) {
            int q = tid + p * 256;
            int n = q >> 3, c8 = (q & 7) * 8;
            size_t gi = (size_t)n * I_DIM + kk + c8;
            int so = n * AS + c8;
            *(uint4*)(Bh + so) = *(const uint4*)(wdh + gi);
            *(uint4*)(Bl + so) = *(const uint4*)(wdl + gi);
        }
        __syncthreads();

#pragma unroll
        for (int ks = 0; ks < 4; ks++) {
            uint32_t ah[2][4];
#pragma unroll
            for (int mf = 0; mf < 2; mf++) {
                int so = (wm*32 + mf*16 + lr) * AS + ks*16 + lc;
                ldsm_x4(ah[mf], smem_u32(Ah + so));
            }
            uint32_t bh[2][4], bl[2][4];
#pragma unroll
            for (int n2 = 0; n2 < 2; n2++) {
                int so = (wn*32 + n2*16 + lr) * AS + ks*16 + lc;
                ldsm_x4(bh[n2], smem_u32(Bh + so));
                ldsm_x4(bl[n2], smem_u32(Bl + so));
            }
#pragma unroll
            for (int mf = 0; mf < 2; mf++)
#pragma unroll
            for (int nf = 0; nf < 4; nf++) {
                int n2 = nf >> 1, nh = nf & 1;
                uint32_t bH[2] = { bh[n2][nh], bh[n2][nh+2] };
                uint32_t bL[2] = { bl[n2][nh], bl[n2][nh+2] };
                mma_fp16(cc[mf][nf], ah[mf], bH);
                mma_fp16(cc[mf][nf], ah[mf], bL);
            }
        }
    }

    // epilogue: store unscaled y rows (fp32)
#pragma unroll
    for (int mf = 0; mf < 2; mf++)
#pragma unroll
    for (int nf = 0; nf < 4; nf++) {
        int col = nt*64 + wn*32 + nf*8 + (lane & 3)*2;
#pragma unroll
        for (int half = 0; half < 2; half++) {
            int row = mt*128 + wm*32 + mf*16 + (lane >> 2) + half*8;
            if (row < cnt) {
                float2 v = make_float2(cc[mf][nf][half*2], cc[mf][nf][half*2+1]);
                *(float2*)(g_y + (size_t)(off + row) * H_DIM + col) = v;
            }
        }
    }
}

// ---------------------------------------------------------------------------
__global__ __launch_bounds__(256) void combine_kernel(float* __restrict__ out)
{
    const int t = blockIdx.x;
    const int tid = threadIdx.x;
    const int e0 = g_te[2*t],   p0 = g_tp[2*t];
    const int e1 = g_te[2*t+1], p1 = g_tp[2*t+1];
    const float w0 = g_tw[2*t], w1 = g_tw[2*t+1];
    const float* y0 = g_y + (size_t)(g_off[e0] + p0) * H_DIM;
    const float* y1 = g_y + (size_t)(g_off[e1] + p1) * H_DIM;
    float* o = out + (size_t)t * H_DIM;
#pragma unroll
    for (int it = 0; it < 2; it++) {
        int i = (tid + it * 256) * 4;
        float4 a = *(const float4*)(y0 + i);
        float4 b = *(const float4*)(y1 + i);
        float4 r;
        r.x = w0 * a.x + w1 * b.x;
        r.y = w0 * a.y + w1 * b.y;
        r.z = w0 * a.z + w1 * b.z;
        r.w = w0 * a.w + w1 * b.w;
        *(float4*)(o + i) = r;
    }
}

// ---------------------------------------------------------------------------
extern "C" void kernel_launch(void* const* d_in, const int* in_sizes, int n_in,
                              void* d_out, int out_size)
{
    const float* hs   = (const float*)d_in[0];
    const float* rmsw = (const float*)d_in[1];
    const float* rw   = (const float*)d_in[2];
    const float* wg   = (const float*)d_in[3];
    const float* wu   = (const float*)d_in[4];
    const float* wd   = (const float*)d_in[5];

    float* out        = (float*)d_out;
    float* out_logits = (float*)d_out + (size_t)T_TOKENS * H_DIM;

    cudaFuncSetAttribute(gemm1_kernel, cudaFuncAttributeMaxDynamicSharedMemorySize, G1_SMEM);
    cudaFuncSetAttribute(gemm2_kernel, cudaFuncAttributeMaxDynamicSharedMemorySize, G2_SMEM);

    // pre-split weights into fp16 hi/lo
    {
        __half *wgh, *wgl, *wuh, *wul, *wdh, *wdl;
        cudaGetSymbolAddress((void**)&wgh, g_wg_hi);
        cudaGetSymbolAddress((void**)&wgl, g_wg_lo);
        cudaGetSymbolAddress((void**)&wuh, g_wu_hi);
        cudaGetSymbolAddress((void**)&wul, g_wu_lo);
        cudaGetSymbolAddress((void**)&wdh, g_wd_hi);
        cudaGetSymbolAddress((void**)&wdl, g_wd_lo);
        int n4 = WELEMS / 4;
        int blocks = (n4 + 255) / 256;
        split_kernel<<<blocks, 256>>>(wg, wgh, wgl, n4);
        split_kernel<<<blocks, 256>>>(wu, wuh, wul, n4);
        split_kernel<<<blocks, 256>>>(wd, wdh, wdl, n4);
    }

    reset_kernel<<<1, 32>>>();
    router_kernel<<<T_TOKENS, 256>>>(hs, rmsw, rw, out_logits);
    offsets_kernel<<<1, 1>>>();

    dim3 g1(I_DIM / 64, T_TOKENS / 128, N_EXP);   // 22 x 64 x 8
    gemm1_kernel<<<g1, 256, G1_SMEM>>>();

    dim3 g2(H_DIM / 64, T_TOKENS / 128, N_EXP);   // 32 x 64 x 8
    gemm2_kernel<<<g2, 256, G2_SMEM>>>();

    combine_kernel<<<T_TOKENS, 256>>>(out);
}

// round 8
// speedup vs baseline: 1.3632x; 1.0142x over previous
#include <cuda_runtime.h>
#include <cuda_fp16.h>
#include <math.h>
#include <stdint.h>

#define T_TOKENS 8192
#define H_DIM    2048
#define I_DIM    1408
#define N_EXP    8
#define MAXTOK   8192
#define TOTROWS  (2*T_TOKENS)
#define WELEMS   (N_EXP * I_DIM * H_DIM)
#define SPLIT_N4 (WELEMS / 4)              // 5,767,168 uint4-groups per weight
#define SPLIT_BLOCKS ((SPLIT_N4 + 255) / 256)

// ---------------- scratch (static device globals) ----------------
__device__ __half g_xn[(size_t)T_TOKENS*H_DIM];
__device__ __half g_h [(size_t)(TOTROWS+128)*I_DIM];
__device__ float  g_y [(size_t)TOTROWS*H_DIM];
__device__ int    g_cnt[N_EXP];
__device__ int    g_off[N_EXP];
__device__ int    g_tok[N_EXP*MAXTOK];
__device__ int    g_te[2*T_TOKENS];
__device__ int    g_tp[2*T_TOKENS];
__device__ float  g_tw[2*T_TOKENS];
// pre-split weights (hi/lo fp16)
__device__ __half g_wg_hi[(size_t)WELEMS];
__device__ __half g_wg_lo[(size_t)WELEMS];
__device__ __half g_wu_hi[(size_t)WELEMS];
__device__ __half g_wu_lo[(size_t)WELEMS];
__device__ __half g_wd_hi[(size_t)WELEMS];
__device__ __half g_wd_lo[(size_t)WELEMS];

// ---------------- helpers ----------------
__device__ __forceinline__ uint32_t smem_u32(const void* p) {
    uint32_t a;
    asm("{ .reg .u64 t; cvta.to.shared.u64 t, %1; cvt.u32.u64 %0, t; }" : "=r"(a) : "l"(p));
    return a;
}
__device__ __forceinline__ void ldsm_x4(uint32_t* r, uint32_t addr) {
    asm volatile("ldmatrix.sync.aligned.m8n8.x4.shared.b16 {%0,%1,%2,%3}, [%4];"
        : "=r"(r[0]), "=r"(r[1]), "=r"(r[2]), "=r"(r[3]) : "r"(addr));
}
__device__ __forceinline__ void mma_fp16(float* c, const uint32_t* a, const uint32_t* b) {
    asm volatile(
        "mma.sync.aligned.m16n8k16.row.col.f32.f16.f16.f32 "
        "{%0,%1,%2,%3}, {%4,%5,%6,%7}, {%8,%9}, {%0,%1,%2,%3};"
        : "+f"(c[0]), "+f"(c[1]), "+f"(c[2]), "+f"(c[3])
        : "r"(a[0]), "r"(a[1]), "r"(a[2]), "r"(a[3]), "r"(b[0]), "r"(b[1]));
}
__device__ __forceinline__ void split_fp16(float x, __half& h, __half& l) {
    h = __float2half_rn(x);
    l = __float2half_rn(x - __half2float(h));
}
__device__ __forceinline__ uint32_t packh2(__half a, __half b) {
    __half2 v = __halves2half2(a, b);
    return *reinterpret_cast<uint32_t*>(&v);
}
__device__ __forceinline__ float warp_sum(float v) {
#pragma unroll
    for (int o = 16; o > 0; o >>= 1)
        v += __shfl_xor_sync(0xFFFFFFFFu, v, o);
    return v;
}

// ---------------------------------------------------------------------------
__global__ void reset_kernel() {
    if (threadIdx.x < N_EXP) g_cnt[threadIdx.x] = 0;
}

// ---------------------------------------------------------------------------
// Fused prep kernel:
//   blocks [0, T_TOKENS)                -> router (RMSNorm + logits + top-2)
//   blocks [T_TOKENS, +3*SPLIT_BLOCKS)  -> weight split fp32 -> fp16 hi/lo
__global__ __launch_bounds__(256) void prep_kernel(
    const float* __restrict__ hs,
    const float* __restrict__ rmsw,
    const float* __restrict__ rw,
    const float* __restrict__ wg,
    const float* __restrict__ wu,
    const float* __restrict__ wd,
    float* __restrict__ out_logits)
{
    const int tid = threadIdx.x;

    if (blockIdx.x >= T_TOKENS) {
        // ---------------- weight split part ----------------
        int sb = blockIdx.x - T_TOKENS;
        int w = sb / SPLIT_BLOCKS;          // 0=wg, 1=wu, 2=wd
        int i = (sb - w * SPLIT_BLOCKS) * 256 + tid;
        if (i >= SPLIT_N4) return;
        const float* src = (w == 0) ? wg : (w == 1) ? wu : wd;
        __half* hi = (w == 0) ? g_wg_hi : (w == 1) ? g_wu_hi : g_wd_hi;
        __half* lo = (w == 0) ? g_wg_lo : (w == 1) ? g_wu_lo : g_wd_lo;
        float4 v = ((const float4*)src)[i];
        __half h0,l0,h1,l1,h2,l2,h3,l3;
        split_fp16(v.x,h0,l0); split_fp16(v.y,h1,l1);
        split_fp16(v.z,h2,l2); split_fp16(v.w,h3,l3);
        ((uint2*)hi)[i] = make_uint2(packh2(h0,h1), packh2(h2,h3));
        ((uint2*)lo)[i] = make_uint2(packh2(l0,l1), packh2(l2,l3));
        return;
    }

    // ---------------- router part ----------------
    const int t    = blockIdx.x;
    const int wid  = tid >> 5;
    const int lane = tid & 31;
    const float* x = hs + (size_t)t * H_DIM;

    __shared__ float swred[8];          // per-warp partials (ss)
    __shared__ float sacc[8][N_EXP];    // per-warp partials (logits)
    __shared__ float s_scale;
    __shared__ float slog[N_EXP];

    // sum of squares -> scale
    float ss = 0.f;
    for (int i = tid; i < H_DIM; i += 256) { float v = x[i]; ss += v * v; }
    ss = warp_sum(ss);
    if (lane == 0) swred[wid] = ss;
    __syncthreads();
    if (tid == 0) {
        float tot = 0.f;
#pragma unroll
        for (int w = 0; w < 8; w++) tot += swred[w];
        s_scale = rsqrtf(tot / (float)H_DIM + 1e-6f);
    }
    __syncthreads();
    const float scale = s_scale;

    // normalized activations (fp16) + 8 router dot products
    float acc[N_EXP];
#pragma unroll
    for (int e = 0; e < N_EXP; e++) acc[e] = 0.f;
    for (int i = tid; i < H_DIM; i += 256) {
        float v = x[i] * scale * rmsw[i];
        g_xn[(size_t)t * H_DIM + i] = __float2half_rn(v);
#pragma unroll
        for (int e = 0; e < N_EXP; e++) acc[e] += v * rw[e * H_DIM + i];
    }
#pragma unroll
    for (int e = 0; e < N_EXP; e++) {
        float v = warp_sum(acc[e]);
        if (lane == 0) sacc[wid][e] = v;
    }
    __syncthreads();
    if (tid < N_EXP) {
        float tot = 0.f;
#pragma unroll
        for (int w = 0; w < 8; w++) tot += sacc[w][tid];
        slog[tid] = tot;
    }
    __syncthreads();

    if (tid == 0) {
        float l[N_EXP], m = -1e30f;
#pragma unroll
        for (int e = 0; e < N_EXP; e++) {
            l[e] = slog[e];
            out_logits[(size_t)t * N_EXP + e] = l[e];
            m = fmaxf(m, l[e]);
        }
        float p[N_EXP], s = 0.f;
#pragma unroll
        for (int e = 0; e < N_EXP; e++) { p[e] = expf(l[e] - m); s += p[e]; }
#pragma unroll
        for (int e = 0; e < N_EXP; e++) p[e] /= s;

        int a = 0;
#pragma unroll
        for (int e = 1; e < N_EXP; e++) if (p[e] > p[a]) a = e;
        int b = (a == 0) ? 1 : 0;
#pragma unroll
        for (int e = 0; e < N_EXP; e++) if (e != a && p[e] > p[b]) b = e;

        float wsum = p[a] + p[b] + 1e-20f;
        float wa = p[a] / wsum, wb = p[b] / wsum;

        int pa = atomicAdd(&g_cnt[a], 1);
        g_tok[a * MAXTOK + pa] = t;
        g_te[2*t] = a; g_tp[2*t] = pa; g_tw[2*t] = wa;
        int pb = atomicAdd(&g_cnt[b], 1);
        g_tok[b * MAXTOK + pb] = t;
        g_te[2*t+1] = b; g_tp[2*t+1] = pb; g_tw[2*t+1] = wb;
    }
}

// ---------------------------------------------------------------------------
__global__ void offsets_kernel() {
    int run = 0;
    for (int e = 0; e < N_EXP; e++) { g_off[e] = run; run += g_cnt[e]; }
}

// ---------------------------------------------------------------------------
// Tiled fp16x2 HMMA GEMMs (round-7 champion, unchanged).
// Block tile 128(M) x 64(N), K-tile 64, 256 threads, warp grid 4x2 (warp 32x32).
// A: single fp16. B: fp16 hi + lo. D = A*Bh + A*Bl.
#define AS 72
#define G1_SMEM ((128*AS + 4*64*AS) * 2)   // 55296 B
#define G2_SMEM ((128*AS + 2*64*AS) * 2)   // 36864 B

__global__ __launch_bounds__(256) void gemm1_kernel()
{
    const int e  = blockIdx.z;
    const int mt = blockIdx.y;
    const int nt = blockIdx.x;
    const int cnt = g_cnt[e];
    if (mt * 128 >= cnt) return;
    const int tid = threadIdx.x;
    const int wid = tid >> 5;
    const int lane = tid & 31;

    extern __shared__ __half sm[];
    __shared__ int stok[128];
    __half* Ah  = sm;
    __half* Bgh = sm + 128*AS;
    __half* Bgl = Bgh + 64*AS;
    __half* Buh = Bgl + 64*AS;
    __half* Bul = Buh + 64*AS;

    if (tid < 128) {
        int row = mt * 128 + tid;
        stok[tid] = (row < cnt) ? g_tok[e * MAXTOK + row] : -1;
    }

    const size_t wbase = (size_t)e * I_DIM * H_DIM + (size_t)(nt * 64) * H_DIM;
    const __half* wgh = g_wg_hi + wbase;
    const __half* wgl = g_wg_lo + wbase;
    const __half* wuh = g_wu_hi + wbase;
    const __half* wul = g_wu_lo + wbase;

    float cg[2][4][4], cu[2][4][4];
#pragma unroll
    for (int i = 0; i < 2; i++)
#pragma unroll
        for (int j = 0; j < 4; j++)
#pragma unroll
            for (int k = 0; k < 4; k++) { cg[i][j][k] = 0.f; cu[i][j][k] = 0.f; }

    const int wm = wid >> 1;
    const int wn = wid & 1;
    const int lr = lane & 15;
    const int lc = (lane >> 4) * 8;

    for (int kk = 0; kk < H_DIM; kk += 64) {
        __syncthreads();
#pragma unroll
        for (int p = 0; p < 4; p++) {
            int q = tid + p * 256;
            int r = q >> 3, c8 = (q & 7) * 8;
            int tok = stok[r];
            uint4 vh = make_uint4(0,0,0,0);
            if (tok >= 0) vh = *(const uint4*)(g_xn + (size_t)tok * H_DIM + kk + c8);
            *(uint4*)(Ah + r * AS + c8) = vh;
        }
#pragma unroll
        for (int p = 0; p < 2; p++) {
            int q = tid + p * 256;
            int n = q >> 3, c8 = (q & 7) * 8;
            size_t gi = (size_t)n * H_DIM + kk + c8;
            int so = n * AS + c8;
            *(uint4*)(Bgh + so) = *(const uint4*)(wgh + gi);
            *(uint4*)(Bgl + so) = *(const uint4*)(wgl + gi);
            *(uint4*)(Buh + so) = *(const uint4*)(wuh + gi);
            *(uint4*)(Bul + so) = *(const uint4*)(wul + gi);
        }
        __syncthreads();

#pragma unroll
        for (int ks = 0; ks < 4; ks++) {
            uint32_t ah[2][4];
#pragma unroll
            for (int mf = 0; mf < 2; mf++) {
                int so = (wm*32 + mf*16 + lr) * AS + ks*16 + lc;
                ldsm_x4(ah[mf], smem_u32(Ah + so));
            }
            uint32_t bgh[2][4], bgl[2][4], buh[2][4], bul[2][4];
#pragma unroll
            for (int n2 = 0; n2 < 2; n2++) {
                int so = (wn*32 + n2*16 + lr) * AS + ks*16 + lc;
                ldsm_x4(bgh[n2], smem_u32(Bgh + so));
                ldsm_x4(bgl[n2], smem_u32(Bgl + so));
                ldsm_x4(buh[n2], smem_u32(Buh + so));
                ldsm_x4(bul[n2], smem_u32(Bul + so));
            }
#pragma unroll
            for (int mf = 0; mf < 2; mf++)
#pragma unroll
            for (int nf = 0; nf < 4; nf++) {
                int n2 = nf >> 1, nh = nf & 1;
                uint32_t bG [2] = { bgh[n2][nh], bgh[n2][nh+2] };
                uint32_t bGl[2] = { bgl[n2][nh], bgl[n2][nh+2] };
                uint32_t bU [2] = { buh[n2][nh], buh[n2][nh+2] };
                uint32_t bUl[2] = { bul[n2][nh], bul[n2][nh+2] };
                mma_fp16(cg[mf][nf], ah[mf], bG);
                mma_fp16(cu[mf][nf], ah[mf], bU);
                mma_fp16(cg[mf][nf], ah[mf], bGl);
                mma_fp16(cu[mf][nf], ah[mf], bUl);
            }
        }
    }

    const int off = g_off[e];
#pragma unroll
    for (int mf = 0; mf < 2; mf++)
#pragma unroll
    for (int nf = 0; nf < 4; nf++) {
        int col = nt*64 + wn*32 + nf*8 + (lane & 3)*2;
#pragma unroll
        for (int half = 0; half < 2; half++) {
            int row = mt*128 + wm*32 + mf*16 + (lane >> 2) + half*8;
            if (row < cnt) {
                float g0 = cg[mf][nf][half*2],   g1 = cg[mf][nf][half*2+1];
                float u0 = cu[mf][nf][half*2],   u1 = cu[mf][nf][half*2+1];
                float h0 = (g0 / (1.f + expf(-g0))) * u0;
                float h1 = (g1 / (1.f + expf(-g1))) * u1;
                size_t base = (size_t)(off + row) * I_DIM + col;
                *(uint32_t*)(g_h + base) = packh2(__float2half_rn(h0), __float2half_rn(h1));
            }
        }
    }
}

// ---------------------------------------------------------------------------
__global__ __launch_bounds__(256) void gemm2_kernel()
{
    const int e  = blockIdx.z;
    const int mt = blockIdx.y;
    const int nt = blockIdx.x;
    const int cnt = g_cnt[e];
    if (mt * 128 >= cnt) return;
    const int tid = threadIdx.x;
    const int wid = tid >> 5;
    const int lane = tid & 31;
    const int off = g_off[e];

    extern __shared__ __half sm[];
    __half* Ah = sm;
    __half* Bh = sm + 128*AS;
    __half* Bl = Bh + 64*AS;

    const size_t wbase = (size_t)e * H_DIM * I_DIM + (size_t)(nt * 64) * I_DIM;
    const __half* wdh = g_wd_hi + wbase;
    const __half* wdl = g_wd_lo + wbase;

    float cc[2][4][4];
#pragma unroll
    for (int i = 0; i < 2; i++)
#pragma unroll
        for (int j = 0; j < 4; j++)
#pragma unroll
            for (int k = 0; k < 4; k++) cc[i][j][k] = 0.f;

    const int wm = wid >> 1;
    const int wn = wid & 1;
    const int lr = lane & 15;
    const int lc = (lane >> 4) * 8;

    for (int kk = 0; kk < I_DIM; kk += 64) {
        __syncthreads();
#pragma unroll
        for (int p = 0; p < 4; p++) {
            int q = tid + p * 256;
            int r = q >> 3, c8 = (q & 7) * 8;
            uint4 vh = *(const uint4*)(g_h + (size_t)(off + mt*128 + r) * I_DIM + kk + c8);
            *(uint4*)(Ah + r * AS + c8) = vh;
        }
#pragma unroll
        for (int p = 0; p < 2; p++) {
            int q = tid + p * 256;
            int n = q >> 3, c8 = (q & 7) * 8;
            size_t gi = (size_t)n * I_DIM + kk + c8;
            int so = n * AS + c8;
            *(uint4*)(Bh + so) = *(const uint4*)(wdh + gi);
            *(uint4*)(Bl + so) = *(const uint4*)(wdl + gi);
        }
        __syncthreads();

#pragma unroll
        for (int ks = 0; ks < 4; ks++) {
            uint32_t ah[2][4];
#pragma unroll
            for (int mf = 0; mf < 2; mf++) {
                int so = (wm*32 + mf*16 + lr) * AS + ks*16 + lc;
                ldsm_x4(ah[mf], smem_u32(Ah + so));
            }
            uint32_t bh[2][4], bl[2][4];
#pragma unroll
            for (int n2 = 0; n2 < 2; n2++) {
                int so = (wn*32 + n2*16 + lr) * AS + ks*16 + lc;
                ldsm_x4(bh[n2], smem_u32(Bh + so));
                ldsm_x4(bl[n2], smem_u32(Bl + so));
            }
#pragma unroll
            for (int mf = 0; mf < 2; mf++)
#pragma unroll
            for (int nf = 0; nf < 4; nf++) {
                int n2 = nf >> 1, nh = nf & 1;
                uint32_t bH[2] = { bh[n2][nh], bh[n2][nh+2] };
                uint32_t bL[2] = { bl[n2][nh], bl[n2][nh+2] };
                mma_fp16(cc[mf][nf], ah[mf], bH);
                mma_fp16(cc[mf][nf], ah[mf], bL);
            }
        }
    }

#pragma unroll
    for (int mf = 0; mf < 2; mf++)
#pragma unroll
    for (int nf = 0; nf < 4; nf++) {
        int col = nt*64 + wn*32 + nf*8 + (lane & 3)*2;
#pragma unroll
        for (int half = 0; half < 2; half++) {
            int row = mt*128 + wm*32 + mf*16 + (lane >> 2) + half*8;
            if (row < cnt) {
                float2 v = make_float2(cc[mf][nf][half*2], cc[mf][nf][half*2+1]);
                *(float2*)(g_y + (size_t)(off + row) * H_DIM + col) = v;
            }
        }
    }
}

// ---------------------------------------------------------------------------
__global__ __launch_bounds__(256) void combine_kernel(float* __restrict__ out)
{
    const int t = blockIdx.x;
    const int tid = threadIdx.x;
    const int e0 = g_te[2*t],   p0 = g_tp[2*t];
    const int e1 = g_te[2*t+1], p1 = g_tp[2*t+1];
    const float w0 = g_tw[2*t], w1 = g_tw[2*t+1];
    const float* y0 = g_y + (size_t)(g_off[e0] + p0) * H_DIM;
    const float* y1 = g_y + (size_t)(g_off[e1] + p1) * H_DIM;
    float* o = out + (size_t)t * H_DIM;
#pragma unroll
    for (int it = 0; it < 2; it++) {
        int i = (tid + it * 256) * 4;
        float4 a = *(const float4*)(y0 + i);
        float4 b = *(const float4*)(y1 + i);
        float4 r;
        r.x = w0 * a.x + w1 * b.x;
        r.y = w0 * a.y + w1 * b.y;
        r.z = w0 * a.z + w1 * b.z;
        r.w = w0 * a.w + w1 * b.w;
        *(float4*)(o + i) = r;
    }
}

// ---------------------------------------------------------------------------
extern "C" void kernel_launch(void* const* d_in, const int* in_sizes, int n_in,
                              void* d_out, int out_size)
{
    const float* hs   = (const float*)d_in[0];
    const float* rmsw = (const float*)d_in[1];
    const float* rw   = (const float*)d_in[2];
    const float* wg   = (const float*)d_in[3];
    const float* wu   = (const float*)d_in[4];
    const float* wd   = (const float*)d_in[5];

    float* out        = (float*)d_out;
    float* out_logits = (float*)d_out + (size_t)T_TOKENS * H_DIM;

    cudaFuncSetAttribute(gemm1_kernel, cudaFuncAttributeMaxDynamicSharedMemorySize, G1_SMEM);
    cudaFuncSetAttribute(gemm2_kernel, cudaFuncAttributeMaxDynamicSharedMemorySize, G2_SMEM);

    reset_kernel<<<1, 32>>>();

    // fused router + weight-split
    int grid = T_TOKENS + 3 * SPLIT_BLOCKS;
    prep_kernel<<<grid, 256>>>(hs, rmsw, rw, wg, wu, wd, out_logits);

    offsets_kernel<<<1, 1>>>();

    dim3 g1(I_DIM / 64, T_TOKENS / 128, N_EXP);   // 22 x 64 x 8
    gemm1_kernel<<<g1, 256, G1_SMEM>>>();

    dim3 g2(H_DIM / 64, T_TOKENS / 128, N_EXP);   // 32 x 64 x 8
    gemm2_kernel<<<g2, 256, G2_SMEM>>>();

    combine_kernel<<<T_TOKENS, 256>>>(out);
}

// round 9
// speedup vs baseline: 1.5525x; 1.1389x over previous
#include <cuda_runtime.h>
#include <cuda_fp16.h>
#include <math.h>
#include <stdint.h>

#define T_TOKENS 8192
#define H_DIM    2048
#define I_DIM    1408
#define N_EXP    8
#define MAXTOK   8192
#define TOTROWS  (2*T_TOKENS)
#define WELEMS   (N_EXP * I_DIM * H_DIM)
#define SPLIT_N4 (WELEMS / 4)
#define SPLIT_BLOCKS ((SPLIT_N4 + 255) / 256)

// ---------------- scratch (static device globals) ----------------
__device__ __half g_xn[(size_t)T_TOKENS*H_DIM];
__device__ __half g_h [(size_t)(TOTROWS+128)*I_DIM];
__device__ float  g_y [(size_t)TOTROWS*H_DIM];
__device__ int    g_cnt[N_EXP];
__device__ int    g_off[N_EXP];
__device__ int    g_tok[N_EXP*MAXTOK];
__device__ int    g_te[2*T_TOKENS];
__device__ int    g_tp[2*T_TOKENS];
__device__ float  g_tw[2*T_TOKENS];
__device__ __half g_wg_hi[(size_t)WELEMS];
__device__ __half g_wg_lo[(size_t)WELEMS];
__device__ __half g_wu_hi[(size_t)WELEMS];
__device__ __half g_wu_lo[(size_t)WELEMS];
__device__ __half g_wd_hi[(size_t)WELEMS];
__device__ __half g_wd_lo[(size_t)WELEMS];

// ---------------- helpers ----------------
__device__ __forceinline__ uint32_t smem_u32(const void* p) {
    uint32_t a;
    asm("{ .reg .u64 t; cvta.to.shared.u64 t, %1; cvt.u32.u64 %0, t; }" : "=r"(a) : "l"(p));
    return a;
}
__device__ __forceinline__ void ldsm_x4(uint32_t* r, uint32_t addr) {
    asm volatile("ldmatrix.sync.aligned.m8n8.x4.shared.b16 {%0,%1,%2,%3}, [%4];"
        : "=r"(r[0]), "=r"(r[1]), "=r"(r[2]), "=r"(r[3]) : "r"(addr));
}
__device__ __forceinline__ void mma_fp16(float* c, const uint32_t* a, const uint32_t* b) {
    asm volatile(
        "mma.sync.aligned.m16n8k16.row.col.f32.f16.f16.f32 "
        "{%0,%1,%2,%3}, {%4,%5,%6,%7}, {%8,%9}, {%0,%1,%2,%3};"
        : "+f"(c[0]), "+f"(c[1]), "+f"(c[2]), "+f"(c[3])
        : "r"(a[0]), "r"(a[1]), "r"(a[2]), "r"(a[3]), "r"(b[0]), "r"(b[1]));
}
__device__ __forceinline__ void cp16(uint32_t dst, const void* src, uint32_t sz) {
    asm volatile("cp.async.cg.shared.global [%0], [%1], 16, %2;"
        :: "r"(dst), "l"(src), "r"(sz) : "memory");
}
#define CP_COMMIT() asm volatile("cp.async.commit_group;" ::: "memory")
template<int N> __device__ __forceinline__ void cp_wait() {
    asm volatile("cp.async.wait_group %0;" :: "n"(N) : "memory");
}
__device__ __forceinline__ void split_fp16(float x, __half& h, __half& l) {
    h = __float2half_rn(x);
    l = __float2half_rn(x - __half2float(h));
}
__device__ __forceinline__ uint32_t packh2(__half a, __half b) {
    __half2 v = __halves2half2(a, b);
    return *reinterpret_cast<uint32_t*>(&v);
}
__device__ __forceinline__ float warp_sum(float v) {
#pragma unroll
    for (int o = 16; o > 0; o >>= 1)
        v += __shfl_xor_sync(0xFFFFFFFFu, v, o);
    return v;
}

// ---------------------------------------------------------------------------
__global__ void reset_kernel() {
    if (threadIdx.x < N_EXP) g_cnt[threadIdx.x] = 0;
}

// ---------------------------------------------------------------------------
// Fused prep kernel: router blocks + weight-split blocks (round-8 structure).
__global__ __launch_bounds__(256) void prep_kernel(
    const float* __restrict__ hs,
    const float* __restrict__ rmsw,
    const float* __restrict__ rw,
    const float* __restrict__ wg,
    const float* __restrict__ wu,
    const float* __restrict__ wd,
    float* __restrict__ out_logits)
{
    const int tid = threadIdx.x;

    if (blockIdx.x >= T_TOKENS) {
        int sb = blockIdx.x - T_TOKENS;
        int w = sb / SPLIT_BLOCKS;
        int i = (sb - w * SPLIT_BLOCKS) * 256 + tid;
        if (i >= SPLIT_N4) return;
        const float* src = (w == 0) ? wg : (w == 1) ? wu : wd;
        __half* hi = (w == 0) ? g_wg_hi : (w == 1) ? g_wu_hi : g_wd_hi;
        __half* lo = (w == 0) ? g_wg_lo : (w == 1) ? g_wu_lo : g_wd_lo;
        float4 v = ((const float4*)src)[i];
        __half h0,l0,h1,l1,h2,l2,h3,l3;
        split_fp16(v.x,h0,l0); split_fp16(v.y,h1,l1);
        split_fp16(v.z,h2,l2); split_fp16(v.w,h3,l3);
        ((uint2*)hi)[i] = make_uint2(packh2(h0,h1), packh2(h2,h3));
        ((uint2*)lo)[i] = make_uint2(packh2(l0,l1), packh2(l2,l3));
        return;
    }

    const int t    = blockIdx.x;
    const int wid  = tid >> 5;
    const int lane = tid & 31;
    const float* x = hs + (size_t)t * H_DIM;

    __shared__ float swred[8];
    __shared__ float sacc[8][N_EXP];
    __shared__ float s_scale;
    __shared__ float slog[N_EXP];

    float ss = 0.f;
    for (int i = tid; i < H_DIM; i += 256) { float v = x[i]; ss += v * v; }
    ss = warp_sum(ss);
    if (lane == 0) swred[wid] = ss;
    __syncthreads();
    if (tid == 0) {
        float tot = 0.f;
#pragma unroll
        for (int w = 0; w < 8; w++) tot += swred[w];
        s_scale = rsqrtf(tot / (float)H_DIM + 1e-6f);
    }
    __syncthreads();
    const float scale = s_scale;

    float acc[N_EXP];
#pragma unroll
    for (int e = 0; e < N_EXP; e++) acc[e] = 0.f;
    for (int i = tid; i < H_DIM; i += 256) {
        float v = x[i] * scale * rmsw[i];
        g_xn[(size_t)t * H_DIM + i] = __float2half_rn(v);
#pragma unroll
        for (int e = 0; e < N_EXP; e++) acc[e] += v * rw[e * H_DIM + i];
    }
#pragma unroll
    for (int e = 0; e < N_EXP; e++) {
        float v = warp_sum(acc[e]);
        if (lane == 0) sacc[wid][e] = v;
    }
    __syncthreads();
    if (tid < N_EXP) {
        float tot = 0.f;
#pragma unroll
        for (int w = 0; w < 8; w++) tot += sacc[w][tid];
        slog[tid] = tot;
    }
    __syncthreads();

    if (tid == 0) {
        float l[N_EXP], m = -1e30f;
#pragma unroll
        for (int e = 0; e < N_EXP; e++) {
            l[e] = slog[e];
            out_logits[(size_t)t * N_EXP + e] = l[e];
            m = fmaxf(m, l[e]);
        }
        float p[N_EXP], s = 0.f;
#pragma unroll
        for (int e = 0; e < N_EXP; e++) { p[e] = expf(l[e] - m); s += p[e]; }
#pragma unroll
        for (int e = 0; e < N_EXP; e++) p[e] /= s;

        int a = 0;
#pragma unroll
        for (int e = 1; e < N_EXP; e++) if (p[e] > p[a]) a = e;
        int b = (a == 0) ? 1 : 0;
#pragma unroll
        for (int e = 0; e < N_EXP; e++) if (e != a && p[e] > p[b]) b = e;

        float wsum = p[a] + p[b] + 1e-20f;
        float wa = p[a] / wsum, wb = p[b] / wsum;

        int pa = atomicAdd(&g_cnt[a], 1);
        g_tok[a * MAXTOK + pa] = t;
        g_te[2*t] = a; g_tp[2*t] = pa; g_tw[2*t] = wa;
        int pb = atomicAdd(&g_cnt[b], 1);
        g_tok[b * MAXTOK + pb] = t;
        g_te[2*t+1] = b; g_tp[2*t+1] = pb; g_tw[2*t+1] = wb;
    }
}

// ---------------------------------------------------------------------------
__global__ void offsets_kernel() {
    int run = 0;
    for (int e = 0; e < N_EXP; e++) { g_off[e] = run; run += g_cnt[e]; }
}

// ---------------------------------------------------------------------------
// fp16x2 HMMA GEMMs, 2-stage cp.async double buffer.
// Block tile 128(M) x 64(N), K-tile 64, 256 threads, warp grid 4x2 (warp 32x32),
// 2 CTAs/SM. MMA/epilogue identical to round-7 champion.
#define AS 72
#define G1_STG_E (384*AS)                  // halves per stage = 27648
#define G1_STG_B (G1_STG_E*2)              // 55296 B
#define G1_SMEM  (2*G1_STG_B)              // 110592 B
#define G2_STG_E (256*AS)                  // 18432
#define G2_STG_B (G2_STG_E*2)              // 36864 B
#define G2_SMEM  (2*G2_STG_B)              // 73728 B

__global__ __launch_bounds__(256, 2) void gemm1_kernel()
{
    const int e  = blockIdx.z;
    const int mt = blockIdx.y;
    const int nt = blockIdx.x;
    const int cnt = g_cnt[e];
    if (mt * 128 >= cnt) return;
    const int tid = threadIdx.x;
    const int wid = tid >> 5;
    const int lane = tid & 31;

    extern __shared__ __half sm[];
    __shared__ int stok[128];

    if (tid < 128) {
        int row = mt * 128 + tid;
        stok[tid] = (row < cnt) ? g_tok[e * MAXTOK + row] : -1;
    }
    __syncthreads();

    const size_t wbase = (size_t)e * I_DIM * H_DIM + (size_t)(nt * 64) * H_DIM;
    const __half* wgh = g_wg_hi + wbase;
    const __half* wgl = g_wg_lo + wbase;
    const __half* wuh = g_wu_hi + wbase;
    const __half* wul = g_wu_lo + wbase;

    const uint32_t smb = smem_u32(sm);

    // hoisted per-thread load coordinates
    const __half* aSrc[4]; uint32_t aDst[4], aSz[4];
#pragma unroll
    for (int p = 0; p < 4; p++) {
        int q = tid + p * 256;
        int r = q >> 3, c8 = (q & 7) * 8;
        int tok = stok[r];
        aSz[p]  = tok >= 0 ? 16u : 0u;
        aSrc[p] = g_xn + (size_t)(tok < 0 ? 0 : tok) * H_DIM + c8;
        aDst[p] = (uint32_t)(r * AS + c8) * 2u;
    }
    size_t bOfs[2]; uint32_t bDst[2];
#pragma unroll
    for (int p = 0; p < 2; p++) {
        int q = tid + p * 256;
        int n = q >> 3, c8 = (q & 7) * 8;
        bOfs[p] = (size_t)n * H_DIM + c8;
        bDst[p] = (uint32_t)(n * AS + c8) * 2u;
    }

#define G1_LOAD(S, KK) do {                                                     \
    uint32_t sb = smb + (S) * G1_STG_B;                                         \
    _Pragma("unroll")                                                           \
    for (int p = 0; p < 4; p++)                                                 \
        cp16(sb + aDst[p], aSrc[p] + (KK), aSz[p]);                             \
    _Pragma("unroll")                                                           \
    for (int p = 0; p < 2; p++) {                                               \
        size_t o = bOfs[p] + (KK);                                              \
        cp16(sb + 128*AS*2 + bDst[p], wgh + o, 16u);                            \
        cp16(sb + 192*AS*2 + bDst[p], wgl + o, 16u);                            \
        cp16(sb + 256*AS*2 + bDst[p], wuh + o, 16u);                            \
        cp16(sb + 320*AS*2 + bDst[p], wul + o, 16u);                            \
    }                                                                           \
} while (0)

    float cg[2][4][4], cu[2][4][4];
#pragma unroll
    for (int i = 0; i < 2; i++)
#pragma unroll
        for (int j = 0; j < 4; j++)
#pragma unroll
            for (int k = 0; k < 4; k++) { cg[i][j][k] = 0.f; cu[i][j][k] = 0.f; }

    const int wm = wid >> 1;
    const int wn = wid & 1;
    const int lr = lane & 15;
    const int lc = (lane >> 4) * 8;

    G1_LOAD(0, 0);
    CP_COMMIT();

    const int KT = H_DIM / 64;
    for (int kt = 0; kt < KT; kt++) {
        const int s = kt & 1;
        if (kt + 1 < KT) {
            G1_LOAD(s ^ 1, (kt + 1) * 64);
            CP_COMMIT();
            cp_wait<1>();
        } else {
            cp_wait<0>();
        }
        __syncthreads();

        const __half* Ah  = sm + s * G1_STG_E;
        const __half* Bgh = Ah + 128*AS;
        const __half* Bgl = Ah + 192*AS;
        const __half* Buh = Ah + 256*AS;
        const __half* Bul = Ah + 320*AS;

#pragma unroll
        for (int ks = 0; ks < 4; ks++) {
            uint32_t ah[2][4];
#pragma unroll
            for (int mf = 0; mf < 2; mf++) {
                int so = (wm*32 + mf*16 + lr) * AS + ks*16 + lc;
                ldsm_x4(ah[mf], smem_u32(Ah + so));
            }
            uint32_t bgh[2][4], bgl[2][4], buh[2][4], bul[2][4];
#pragma unroll
            for (int n2 = 0; n2 < 2; n2++) {
                int so = (wn*32 + n2*16 + lr) * AS + ks*16 + lc;
                ldsm_x4(bgh[n2], smem_u32(Bgh + so));
                ldsm_x4(bgl[n2], smem_u32(Bgl + so));
                ldsm_x4(buh[n2], smem_u32(Buh + so));
                ldsm_x4(bul[n2], smem_u32(Bul + so));
            }
#pragma unroll
            for (int mf = 0; mf < 2; mf++)
#pragma unroll
            for (int nf = 0; nf < 4; nf++) {
                int n2 = nf >> 1, nh = nf & 1;
                uint32_t bG [2] = { bgh[n2][nh], bgh[n2][nh+2] };
                uint32_t bGl[2] = { bgl[n2][nh], bgl[n2][nh+2] };
                uint32_t bU [2] = { buh[n2][nh], buh[n2][nh+2] };
                uint32_t bUl[2] = { bul[n2][nh], bul[n2][nh+2] };
                mma_fp16(cg[mf][nf], ah[mf], bG);
                mma_fp16(cu[mf][nf], ah[mf], bU);
                mma_fp16(cg[mf][nf], ah[mf], bGl);
                mma_fp16(cu[mf][nf], ah[mf], bUl);
            }
        }
        __syncthreads();
    }
#undef G1_LOAD

    const int off = g_off[e];
#pragma unroll
    for (int mf = 0; mf < 2; mf++)
#pragma unroll
    for (int nf = 0; nf < 4; nf++) {
        int col = nt*64 + wn*32 + nf*8 + (lane & 3)*2;
#pragma unroll
        for (int half = 0; half < 2; half++) {
            int row = mt*128 + wm*32 + mf*16 + (lane >> 2) + half*8;
            if (row < cnt) {
                float g0 = cg[mf][nf][half*2],   g1 = cg[mf][nf][half*2+1];
                float u0 = cu[mf][nf][half*2],   u1 = cu[mf][nf][half*2+1];
                float h0 = (g0 / (1.f + expf(-g0))) * u0;
                float h1 = (g1 / (1.f + expf(-g1))) * u1;
                size_t base = (size_t)(off + row) * I_DIM + col;
                *(uint32_t*)(g_h + base) = packh2(__float2half_rn(h0), __float2half_rn(h1));
            }
        }
    }
}

// ---------------------------------------------------------------------------
__global__ __launch_bounds__(256, 2) void gemm2_kernel()
{
    const int e  = blockIdx.z;
    const int mt = blockIdx.y;
    const int nt = blockIdx.x;
    const int cnt = g_cnt[e];
    if (mt * 128 >= cnt) return;
    const int tid = threadIdx.x;
    const int wid = tid >> 5;
    const int lane = tid & 31;
    const int off = g_off[e];

    extern __shared__ __half sm[];

    const size_t wbase = (size_t)e * H_DIM * I_DIM + (size_t)(nt * 64) * I_DIM;
    const __half* wdh = g_wd_hi + wbase;
    const __half* wdl = g_wd_lo + wbase;

    const uint32_t smb = smem_u32(sm);

    const __half* aSrc[4]; uint32_t aDst[4];
#pragma unroll
    for (int p = 0; p < 4; p++) {
        int q = tid + p * 256;
        int r = q >> 3, c8 = (q & 7) * 8;
        aSrc[p] = g_h + (size_t)(off + mt*128 + r) * I_DIM + c8;
        aDst[p] = (uint32_t)(r * AS + c8) * 2u;
    }
    size_t bOfs[2]; uint32_t bDst[2];
#pragma unroll
    for (int p = 0; p < 2; p++) {
        int q = tid + p * 256;
        int n = q >> 3, c8 = (q & 7) * 8;
        bOfs[p] = (size_t)n * I_DIM + c8;
        bDst[p] = (uint32_t)(n * AS + c8) * 2u;
    }

#define G2_LOAD(S, KK) do {                                                     \
    uint32_t sb = smb + (S) * G2_STG_B;                                         \
    _Pragma("unroll")                                                           \
    for (int p = 0; p < 4; p++)                                                 \
        cp16(sb + aDst[p], aSrc[p] + (KK), 16u);                                \
    _Pragma("unroll")                                                           \
    for (int p = 0; p < 2; p++) {                                               \
        size_t o = bOfs[p] + (KK);                                              \
        cp16(sb + 128*AS*2 + bDst[p], wdh + o, 16u);                            \
        cp16(sb + 192*AS*2 + bDst[p], wdl + o, 16u);                            \
    }                                                                           \
} while (0)

    float cc[2][4][4];
#pragma unroll
    for (int i = 0; i < 2; i++)
#pragma unroll
        for (int j = 0; j < 4; j++)
#pragma unroll
            for (int k = 0; k < 4; k++) cc[i][j][k] = 0.f;

    const int wm = wid >> 1;
    const int wn = wid & 1;
    const int lr = lane & 15;
    const int lc = (lane >> 4) * 8;

    G2_LOAD(0, 0);
    CP_COMMIT();

    const int KT = I_DIM / 64;
    for (int kt = 0; kt < KT; kt++) {
        const int s = kt & 1;
        if (kt + 1 < KT) {
            G2_LOAD(s ^ 1, (kt + 1) * 64);
            CP_COMMIT();
            cp_wait<1>();
        } else {
            cp_wait<0>();
        }
        __syncthreads();

        const __half* Ah = sm + s * G2_STG_E;
        const __half* Bh = Ah + 128*AS;
        const __half* Bl = Ah + 192*AS;

#pragma unroll
        for (int ks = 0; ks < 4; ks++) {
            uint32_t ah[2][4];
#pragma unroll
            for (int mf = 0; mf < 2; mf++) {
                int so = (wm*32 + mf*16 + lr) * AS + ks*16 + lc;
                ldsm_x4(ah[mf], smem_u32(Ah + so));
            }
            uint32_t bh[2][4], bl[2][4];
#pragma unroll
            for (int n2 = 0; n2 < 2; n2++) {
                int so = (wn*32 + n2*16 + lr) * AS + ks*16 + lc;
                ldsm_x4(bh[n2], smem_u32(Bh + so));
                ldsm_x4(bl[n2], smem_u32(Bl + so));
            }
#pragma unroll
            for (int mf = 0; mf < 2; mf++)
#pragma unroll
            for (int nf = 0; nf < 4; nf++) {
                int n2 = nf >> 1, nh = nf & 1;
                uint32_t bH[2] = { bh[n2][nh], bh[n2][nh+2] };
                uint32_t bL[2] = { bl[n2][nh], bl[n2][nh+2] };
                mma_fp16(cc[mf][nf], ah[mf], bH);
                mma_fp16(cc[mf][nf], ah[mf], bL);
            }
        }
        __syncthreads();
    }
#undef G2_LOAD

#pragma unroll
    for (int mf = 0; mf < 2; mf++)
#pragma unroll
    for (int nf = 0; nf < 4; nf++) {
        int col = nt*64 + wn*32 + nf*8 + (lane & 3)*2;
#pragma unroll
        for (int half = 0; half < 2; half++) {
            int row = mt*128 + wm*32 + mf*16 + (lane >> 2) + half*8;
            if (row < cnt) {
                float2 v = make_float2(cc[mf][nf][half*2], cc[mf][nf][half*2+1]);
                *(float2*)(g_y + (size_t)(off + row) * H_DIM + col) = v;
            }
        }
    }
}

// ---------------------------------------------------------------------------
__global__ __launch_bounds__(256) void combine_kernel(float* __restrict__ out)
{
    const int t = blockIdx.x;
    const int tid = threadIdx.x;
    const int e0 = g_te[2*t],   p0 = g_tp[2*t];
    const int e1 = g_te[2*t+1], p1 = g_tp[2*t+1];
    const float w0 = g_tw[2*t], w1 = g_tw[2*t+1];
    const float* y0 = g_y + (size_t)(g_off[e0] + p0) * H_DIM;
    const float* y1 = g_y + (size_t)(g_off[e1] + p1) * H_DIM;
    float* o = out + (size_t)t * H_DIM;
#pragma unroll
    for (int it = 0; it < 2; it++) {
        int i = (tid + it * 256) * 4;
        float4 a = *(const float4*)(y0 + i);
        float4 b = *(const float4*)(y1 + i);
        float4 r;
        r.x = w0 * a.x + w1 * b.x;
        r.y = w0 * a.y + w1 * b.y;
        r.z = w0 * a.z + w1 * b.z;
        r.w = w0 * a.w + w1 * b.w;
        *(float4*)(o + i) = r;
    }
}

// ---------------------------------------------------------------------------
extern "C" void kernel_launch(void* const* d_in, const int* in_sizes, int n_in,
                              void* d_out, int out_size)
{
    const float* hs   = (const float*)d_in[0];
    const float* rmsw = (const float*)d_in[1];
    const float* rw   = (const float*)d_in[2];
    const float* wg   = (const float*)d_in[3];
    const float* wu   = (const float*)d_in[4];
    const float* wd   = (const float*)d_in[5];

    float* out        = (float*)d_out;
    float* out_logits = (float*)d_out + (size_t)T_TOKENS * H_DIM;

    cudaFuncSetAttribute(gemm1_kernel, cudaFuncAttributeMaxDynamicSharedMemorySize, G1_SMEM);
    cudaFuncSetAttribute(gemm2_kernel, cudaFuncAttributeMaxDynamicSharedMemorySize, G2_SMEM);

    reset_kernel<<<1, 32>>>();

    int grid = T_TOKENS + 3 * SPLIT_BLOCKS;
    prep_kernel<<<grid, 256>>>(hs, rmsw, rw, wg, wu, wd, out_logits);

    offsets_kernel<<<1, 1>>>();

    dim3 g1(I_DIM / 64, T_TOKENS / 128, N_EXP);   // 22 x 64 x 8
    gemm1_kernel<<<g1, 256, G1_SMEM>>>();

    dim3 g2(H_DIM / 64, T_TOKENS / 128, N_EXP);   // 32 x 64 x 8
    gemm2_kernel<<<g2, 256, G2_SMEM>>>();

    combine_kernel<<<T_TOKENS, 256>>>(out);
}

// round 10
// speedup vs baseline: 2.3297x; 1.5006x over previous
#include <cuda_runtime.h>
#include <cuda_fp16.h>
#include <math.h>
#include <stdint.h>

#define T_TOKENS 8192
#define H_DIM    2048
#define I_DIM    1408
#define N_EXP    8
#define MAXTOK   8192
#define TOTROWS  (2*T_TOKENS)
#define WELEMS   (N_EXP * I_DIM * H_DIM)
#define SPLIT_N4 (WELEMS / 4)
#define SPLIT_BLOCKS ((SPLIT_N4 + 255) / 256)

// ---------------- scratch (static device globals) ----------------
__device__ __half g_xn[(size_t)T_TOKENS*H_DIM];
__device__ __half g_h [(size_t)(TOTROWS+128)*I_DIM];
__device__ float  g_y [(size_t)TOTROWS*H_DIM];
__device__ int    g_cnt[N_EXP];
__device__ int    g_off[N_EXP];
__device__ int    g_tok[N_EXP*MAXTOK];
__device__ int    g_te[2*T_TOKENS];
__device__ int    g_tp[2*T_TOKENS];
__device__ float  g_tw[2*T_TOKENS];
// fp16 weights (single term)
__device__ __half g_wg[(size_t)WELEMS];
__device__ __half g_wu[(size_t)WELEMS];
__device__ __half g_wd[(size_t)WELEMS];

// ---------------- helpers ----------------
__device__ __forceinline__ uint32_t smem_u32(const void* p) {
    uint32_t a;
    asm("{ .reg .u64 t; cvta.to.shared.u64 t, %1; cvt.u32.u64 %0, t; }" : "=r"(a) : "l"(p));
    return a;
}
__device__ __forceinline__ void ldsm_x4(uint32_t* r, uint32_t addr) {
    asm volatile("ldmatrix.sync.aligned.m8n8.x4.shared.b16 {%0,%1,%2,%3}, [%4];"
        : "=r"(r[0]), "=r"(r[1]), "=r"(r[2]), "=r"(r[3]) : "r"(addr));
}
__device__ __forceinline__ void mma_fp16(float* c, const uint32_t* a, const uint32_t* b) {
    asm volatile(
        "mma.sync.aligned.m16n8k16.row.col.f32.f16.f16.f32 "
        "{%0,%1,%2,%3}, {%4,%5,%6,%7}, {%8,%9}, {%0,%1,%2,%3};"
        : "+f"(c[0]), "+f"(c[1]), "+f"(c[2]), "+f"(c[3])
        : "r"(a[0]), "r"(a[1]), "r"(a[2]), "r"(a[3]), "r"(b[0]), "r"(b[1]));
}
__device__ __forceinline__ void cp16(uint32_t dst, const void* src, uint32_t sz) {
    asm volatile("cp.async.cg.shared.global [%0], [%1], 16, %2;"
        :: "r"(dst), "l"(src), "r"(sz) : "memory");
}
#define CP_COMMIT() asm volatile("cp.async.commit_group;" ::: "memory")
template<int N> __device__ __forceinline__ void cp_wait() {
    asm volatile("cp.async.wait_group %0;" :: "n"(N) : "memory");
}
__device__ __forceinline__ uint32_t packh2(__half a, __half b) {
    __half2 v = __halves2half2(a, b);
    return *reinterpret_cast<uint32_t*>(&v);
}
__device__ __forceinline__ float warp_sum(float v) {
#pragma unroll
    for (int o = 16; o > 0; o >>= 1)
        v += __shfl_xor_sync(0xFFFFFFFFu, v, o);
    return v;
}

// ---------------------------------------------------------------------------
__global__ void reset_kernel() {
    if (threadIdx.x < N_EXP) g_cnt[threadIdx.x] = 0;
}

// ---------------------------------------------------------------------------
// Fused prep kernel: router blocks + weight-cast blocks.
__global__ __launch_bounds__(256) void prep_kernel(
    const float* __restrict__ hs,
    const float* __restrict__ rmsw,
    const float* __restrict__ rw,
    const float* __restrict__ wg,
    const float* __restrict__ wu,
    const float* __restrict__ wd,
    float* __restrict__ out_logits)
{
    const int tid = threadIdx.x;

    if (blockIdx.x >= T_TOKENS) {
        int sb = blockIdx.x - T_TOKENS;
        int w = sb / SPLIT_BLOCKS;
        int i = (sb - w * SPLIT_BLOCKS) * 256 + tid;
        if (i >= SPLIT_N4) return;
        const float* src = (w == 0) ? wg : (w == 1) ? wu : wd;
        __half* hi = (w == 0) ? g_wg : (w == 1) ? g_wu : g_wd;
        float4 v = ((const float4*)src)[i];
        ((uint2*)hi)[i] = make_uint2(
            packh2(__float2half_rn(v.x), __float2half_rn(v.y)),
            packh2(__float2half_rn(v.z), __float2half_rn(v.w)));
        return;
    }

    const int t    = blockIdx.x;
    const int wid  = tid >> 5;
    const int lane = tid & 31;
    const float* x = hs + (size_t)t * H_DIM;

    __shared__ float swred[8];
    __shared__ float sacc[8][N_EXP];
    __shared__ float s_scale;
    __shared__ float slog[N_EXP];

    float ss = 0.f;
    for (int i = tid; i < H_DIM; i += 256) { float v = x[i]; ss += v * v; }
    ss = warp_sum(ss);
    if (lane == 0) swred[wid] = ss;
    __syncthreads();
    if (tid == 0) {
        float tot = 0.f;
#pragma unroll
        for (int w = 0; w < 8; w++) tot += swred[w];
        s_scale = rsqrtf(tot / (float)H_DIM + 1e-6f);
    }
    __syncthreads();
    const float scale = s_scale;

    float acc[N_EXP];
#pragma unroll
    for (int e = 0; e < N_EXP; e++) acc[e] = 0.f;
    for (int i = tid; i < H_DIM; i += 256) {
        float v = x[i] * scale * rmsw[i];
        g_xn[(size_t)t * H_DIM + i] = __float2half_rn(v);
#pragma unroll
        for (int e = 0; e < N_EXP; e++) acc[e] += v * rw[e * H_DIM + i];
    }
#pragma unroll
    for (int e = 0; e < N_EXP; e++) {
        float v = warp_sum(acc[e]);
        if (lane == 0) sacc[wid][e] = v;
    }
    __syncthreads();
    if (tid < N_EXP) {
        float tot = 0.f;
#pragma unroll
        for (int w = 0; w < 8; w++) tot += sacc[w][tid];
        slog[tid] = tot;
    }
    __syncthreads();

    if (tid == 0) {
        float l[N_EXP], m = -1e30f;
#pragma unroll
        for (int e = 0; e < N_EXP; e++) {
            l[e] = slog[e];
            out_logits[(size_t)t * N_EXP + e] = l[e];
            m = fmaxf(m, l[e]);
        }
        float p[N_EXP], s = 0.f;
#pragma unroll
        for (int e = 0; e < N_EXP; e++) { p[e] = expf(l[e] - m); s += p[e]; }
#pragma unroll
        for (int e = 0; e < N_EXP; e++) p[e] /= s;

        int a = 0;
#pragma unroll
        for (int e = 1; e < N_EXP; e++) if (p[e] > p[a]) a = e;
        int b = (a == 0) ? 1 : 0;
#pragma unroll
        for (int e = 0; e < N_EXP; e++) if (e != a && p[e] > p[b]) b = e;

        float wsum = p[a] + p[b] + 1e-20f;
        float wa = p[a] / wsum, wb = p[b] / wsum;

        int pa = atomicAdd(&g_cnt[a], 1);
        g_tok[a * MAXTOK + pa] = t;
        g_te[2*t] = a; g_tp[2*t] = pa; g_tw[2*t] = wa;
        int pb = atomicAdd(&g_cnt[b], 1);
        g_tok[b * MAXTOK + pb] = t;
        g_te[2*t+1] = b; g_tp[2*t+1] = pb; g_tw[2*t+1] = wb;
    }
}

// ---------------------------------------------------------------------------
__global__ void offsets_kernel() {
    int run = 0;
    for (int e = 0; e < N_EXP; e++) { g_off[e] = run; run += g_cnt[e]; }
}

// ---------------------------------------------------------------------------
// fp16 HMMA GEMMs (single term), 2-stage cp.async double buffer.
// Block tile 128(M) x 64(N), K-tile 64, 256 threads, warp grid 4x2 (warp 32x32),
// 2 CTAs/SM.
#define AS 72
#define G1_STG_E (256*AS)                  // halves per stage = 18432
#define G1_STG_B (G1_STG_E*2)              // 36864 B
#define G1_SMEM  (2*G1_STG_B)              // 73728 B
#define G2_STG_E (192*AS)                  // 13824
#define G2_STG_B (G2_STG_E*2)              // 27648 B
#define G2_SMEM  (2*G2_STG_B)              // 55296 B

__global__ __launch_bounds__(256, 2) void gemm1_kernel()
{
    const int e  = blockIdx.z;
    const int mt = blockIdx.y;
    const int nt = blockIdx.x;
    const int cnt = g_cnt[e];
    if (mt * 128 >= cnt) return;
    const int tid = threadIdx.x;
    const int wid = tid >> 5;
    const int lane = tid & 31;

    extern __shared__ __half sm[];
    __shared__ int stok[128];

    if (tid < 128) {
        int row = mt * 128 + tid;
        stok[tid] = (row < cnt) ? g_tok[e * MAXTOK + row] : -1;
    }
    __syncthreads();

    const size_t wbase = (size_t)e * I_DIM * H_DIM + (size_t)(nt * 64) * H_DIM;
    const __half* wgp = g_wg + wbase;
    const __half* wup = g_wu + wbase;

    const uint32_t smb = smem_u32(sm);

    // hoisted per-thread load coordinates
    const __half* aSrc[4]; uint32_t aDst[4], aSz[4];
#pragma unroll
    for (int p = 0; p < 4; p++) {
        int q = tid + p * 256;
        int r = q >> 3, c8 = (q & 7) * 8;
        int tok = stok[r];
        aSz[p]  = tok >= 0 ? 16u : 0u;
        aSrc[p] = g_xn + (size_t)(tok < 0 ? 0 : tok) * H_DIM + c8;
        aDst[p] = (uint32_t)(r * AS + c8) * 2u;
    }
    size_t bOfs[2]; uint32_t bDst[2];
#pragma unroll
    for (int p = 0; p < 2; p++) {
        int q = tid + p * 256;
        int n = q >> 3, c8 = (q & 7) * 8;
        bOfs[p] = (size_t)n * H_DIM + c8;
        bDst[p] = (uint32_t)(n * AS + c8) * 2u;
    }

#define G1_LOAD(S, KK) do {                                                     \
    uint32_t sb = smb + (S) * G1_STG_B;                                         \
    _Pragma("unroll")                                                           \
    for (int p = 0; p < 4; p++)                                                 \
        cp16(sb + aDst[p], aSrc[p] + (KK), aSz[p]);                             \
    _Pragma("unroll")                                                           \
    for (int p = 0; p < 2; p++) {                                               \
        size_t o = bOfs[p] + (KK);                                              \
        cp16(sb + 128*AS*2 + bDst[p], wgp + o, 16u);                            \
        cp16(sb + 192*AS*2 + bDst[p], wup + o, 16u);                            \
    }                                                                           \
} while (0)

    float cg[2][4][4], cu[2][4][4];
#pragma unroll
    for (int i = 0; i < 2; i++)
#pragma unroll
        for (int j = 0; j < 4; j++)
#pragma unroll
            for (int k = 0; k < 4; k++) { cg[i][j][k] = 0.f; cu[i][j][k] = 0.f; }

    const int wm = wid >> 1;
    const int wn = wid & 1;
    const int lr = lane & 15;
    const int lc = (lane >> 4) * 8;

    G1_LOAD(0, 0);
    CP_COMMIT();

    const int KT = H_DIM / 64;
#pragma unroll 2
    for (int kt = 0; kt < KT; kt++) {
        const int s = kt & 1;
        if (kt + 1 < KT) {
            G1_LOAD(s ^ 1, (kt + 1) * 64);
            CP_COMMIT();
            cp_wait<1>();
        } else {
            cp_wait<0>();
        }
        __syncthreads();

        const __half* Ah = sm + s * G1_STG_E;
        const __half* Bg = Ah + 128*AS;
        const __half* Bu = Ah + 192*AS;

#pragma unroll
        for (int ks = 0; ks < 4; ks++) {
            uint32_t ah[2][4];
#pragma unroll
            for (int mf = 0; mf < 2; mf++) {
                int so = (wm*32 + mf*16 + lr) * AS + ks*16 + lc;
                ldsm_x4(ah[mf], smem_u32(Ah + so));
            }
            uint32_t bg[2][4], bu[2][4];
#pragma unroll
            for (int n2 = 0; n2 < 2; n2++) {
                int so = (wn*32 + n2*16 + lr) * AS + ks*16 + lc;
                ldsm_x4(bg[n2], smem_u32(Bg + so));
                ldsm_x4(bu[n2], smem_u32(Bu + so));
            }
#pragma unroll
            for (int mf = 0; mf < 2; mf++)
#pragma unroll
            for (int nf = 0; nf < 4; nf++) {
                int n2 = nf >> 1, nh = nf & 1;
                uint32_t bG[2] = { bg[n2][nh], bg[n2][nh+2] };
                uint32_t bU[2] = { bu[n2][nh], bu[n2][nh+2] };
                mma_fp16(cg[mf][nf], ah[mf], bG);
                mma_fp16(cu[mf][nf], ah[mf], bU);
            }
        }
        __syncthreads();
    }
#undef G1_LOAD

    const int off = g_off[e];
#pragma unroll
    for (int mf = 0; mf < 2; mf++)
#pragma unroll
    for (int nf = 0; nf < 4; nf++) {
        int col = nt*64 + wn*32 + nf*8 + (lane & 3)*2;
#pragma unroll
        for (int half = 0; half < 2; half++) {
            int row = mt*128 + wm*32 + mf*16 + (lane >> 2) + half*8;
            if (row < cnt) {
                float g0 = cg[mf][nf][half*2],   g1 = cg[mf][nf][half*2+1];
                float u0 = cu[mf][nf][half*2],   u1 = cu[mf][nf][half*2+1];
                float h0 = (g0 / (1.f + expf(-g0))) * u0;
                float h1 = (g1 / (1.f + expf(-g1))) * u1;
                size_t base = (size_t)(off + row) * I_DIM + col;
                *(uint32_t*)(g_h + base) = packh2(__float2half_rn(h0), __float2half_rn(h1));
            }
        }
    }
}

// ---------------------------------------------------------------------------
__global__ __launch_bounds__(256, 2) void gemm2_kernel()
{
    const int e  = blockIdx.z;
    const int mt = blockIdx.y;
    const int nt = blockIdx.x;
    const int cnt = g_cnt[e];
    if (mt * 128 >= cnt) return;
    const int tid = threadIdx.x;
    const int wid = tid >> 5;
    const int lane = tid & 31;
    const int off = g_off[e];

    extern __shared__ __half sm[];

    const size_t wbase = (size_t)e * H_DIM * I_DIM + (size_t)(nt * 64) * I_DIM;
    const __half* wdp = g_wd + wbase;

    const uint32_t smb = smem_u32(sm);

    const __half* aSrc[4]; uint32_t aDst[4];
#pragma unroll
    for (int p = 0; p < 4; p++) {
        int q = tid + p * 256;
        int r = q >> 3, c8 = (q & 7) * 8;
        aSrc[p] = g_h + (size_t)(off + mt*128 + r) * I_DIM + c8;
        aDst[p] = (uint32_t)(r * AS + c8) * 2u;
    }
    size_t bOfs[2]; uint32_t bDst[2];
#pragma unroll
    for (int p = 0; p < 2; p++) {
        int q = tid + p * 256;
        int n = q >> 3, c8 = (q & 7) * 8;
        bOfs[p] = (size_t)n * I_DIM + c8;
        bDst[p] = (uint32_t)(n * AS + c8) * 2u;
    }

#define G2_LOAD(S, KK) do {                                                     \
    uint32_t sb = smb + (S) * G2_STG_B;                                         \
    _Pragma("unroll")                                                           \
    for (int p = 0; p < 4; p++)                                                 \
        cp16(sb + aDst[p], aSrc[p] + (KK), 16u);                                \
    _Pragma("unroll")                                                           \
    for (int p = 0; p < 2; p++)                                                 \
        cp16(sb + 128*AS*2 + bDst[p], wdp + bOfs[p] + (KK), 16u);               \
} while (0)

    float cc[2][4][4];
#pragma unroll
    for (int i = 0; i < 2; i++)
#pragma unroll
        for (int j = 0; j < 4; j++)
#pragma unroll
            for (int k = 0; k < 4; k++) cc[i][j][k] = 0.f;

    const int wm = wid >> 1;
    const int wn = wid & 1;
    const int lr = lane & 15;
    const int lc = (lane >> 4) * 8;

    G2_LOAD(0, 0);
    CP_COMMIT();

    const int KT = I_DIM / 64;
#pragma unroll 2
    for (int kt = 0; kt < KT; kt++) {
        const int s = kt & 1;
        if (kt + 1 < KT) {
            G2_LOAD(s ^ 1, (kt + 1) * 64);
            CP_COMMIT();
            cp_wait<1>();
        } else {
            cp_wait<0>();
        }
        __syncthreads();

        const __half* Ah = sm + s * G2_STG_E;
        const __half* Bd = Ah + 128*AS;

#pragma unroll
        for (int ks = 0; ks < 4; ks++) {
            uint32_t ah[2][4];
#pragma unroll
            for (int mf = 0; mf < 2; mf++) {
                int so = (wm*32 + mf*16 + lr) * AS + ks*16 + lc;
                ldsm_x4(ah[mf], smem_u32(Ah + so));
            }
            uint32_t bd[2][4];
#pragma unroll
            for (int n2 = 0; n2 < 2; n2++) {
                int so = (wn*32 + n2*16 + lr) * AS + ks*16 + lc;
                ldsm_x4(bd[n2], smem_u32(Bd + so));
            }
#pragma unroll
            for (int mf = 0; mf < 2; mf++)
#pragma unroll
            for (int nf = 0; nf < 4; nf++) {
                int n2 = nf >> 1, nh = nf & 1;
                uint32_t bB[2] = { bd[n2][nh], bd[n2][nh+2] };
                mma_fp16(cc[mf][nf], ah[mf], bB);
            }
        }
        __syncthreads();
    }
#undef G2_LOAD

#pragma unroll
    for (int mf = 0; mf < 2; mf++)
#pragma unroll
    for (int nf = 0; nf < 4; nf++) {
        int col = nt*64 + wn*32 + nf*8 + (lane & 3)*2;
#pragma unroll
        for (int half = 0; half < 2; half++) {
            int row = mt*128 + wm*32 + mf*16 + (lane >> 2) + half*8;
            if (row < cnt) {
                float2 v = make_float2(cc[mf][nf][half*2], cc[mf][nf][half*2+1]);
                *(float2*)(g_y + (size_t)(off + row) * H_DIM + col) = v;
            }
        }
    }
}

// ---------------------------------------------------------------------------
__global__ __launch_bounds__(256) void combine_kernel(float* __restrict__ out)
{
    const int t = blockIdx.x;
    const int tid = threadIdx.x;
    const int e0 = g_te[2*t],   p0 = g_tp[2*t];
    const int e1 = g_te[2*t+1], p1 = g_tp[2*t+1];
    const float w0 = g_tw[2*t], w1 = g_tw[2*t+1];
    const float* y0 = g_y + (size_t)(g_off[e0] + p0) * H_DIM;
    const float* y1 = g_y + (size_t)(g_off[e1] + p1) * H_DIM;
    float* o = out + (size_t)t * H_DIM;
#pragma unroll
    for (int it = 0; it < 2; it++) {
        int i = (tid + it * 256) * 4;
        float4 a = *(const float4*)(y0 + i);
        float4 b = *(const float4*)(y1 + i);
        float4 r;
        r.x = w0 * a.x + w1 * b.x;
        r.y = w0 * a.y + w1 * b.y;
        r.z = w0 * a.z + w1 * b.z;
        r.w = w0 * a.w + w1 * b.w;
        *(float4*)(o + i) = r;
    }
}

// ---------------------------------------------------------------------------
extern "C" void kernel_launch(void* const* d_in, const int* in_sizes, int n_in,
                              void* d_out, int out_size)
{
    const float* hs   = (const float*)d_in[0];
    const float* rmsw = (const float*)d_in[1];
    const float* rw   = (const float*)d_in[2];
    const float* wg   = (const float*)d_in[3];
    const float* wu   = (const float*)d_in[4];
    const float* wd   = (const float*)d_in[5];

    float* out        = (float*)d_out;
    float* out_logits = (float*)d_out + (size_t)T_TOKENS * H_DIM;

    cudaFuncSetAttribute(gemm1_kernel, cudaFuncAttributeMaxDynamicSharedMemorySize, G1_SMEM);
    cudaFuncSetAttribute(gemm2_kernel, cudaFuncAttributeMaxDynamicSharedMemorySize, G2_SMEM);

    reset_kernel<<<1, 32>>>();

    int grid = T_TOKENS + 3 * SPLIT_BLOCKS;
    prep_kernel<<<grid, 256>>>(hs, rmsw, rw, wg, wu, wd, out_logits);

    offsets_kernel<<<1, 1>>>();

    dim3 g1(I_DIM / 64, T_TOKENS / 128, N_EXP);   // 22 x 64 x 8
    gemm1_kernel<<<g1, 256, G1_SMEM>>>();

    dim3 g2(H_DIM / 64, T_TOKENS / 128, N_EXP);   // 32 x 64 x 8
    gemm2_kernel<<<g2, 256, G2_SMEM>>>();

    combine_kernel<<<T_TOKENS, 256>>>(out);
}

// round 11
// speedup vs baseline: 2.4716x; 1.0609x over previous
#include <cuda_runtime.h>
#include <cuda_fp16.h>
#include <math.h>
#include <stdint.h>

#define T_TOKENS 8192
#define H_DIM    2048
#define I_DIM    1408
#define N_EXP    8
#define MAXTOK   8192
#define TOTROWS  (2*T_TOKENS)
#define WELEMS   (N_EXP * I_DIM * H_DIM)
#define SPLIT_N4 (WELEMS / 4)
#define SPLIT_BLOCKS ((SPLIT_N4 + 255) / 256)

// ---------------- scratch (static device globals) ----------------
__device__ __half g_xn[(size_t)T_TOKENS*H_DIM];
__device__ __half g_h [(size_t)(TOTROWS+128)*I_DIM];
__device__ float  g_y [(size_t)TOTROWS*H_DIM];
__device__ int    g_cnt[N_EXP];
__device__ int    g_off[N_EXP];
__device__ int    g_tok[N_EXP*MAXTOK];
__device__ int    g_te[2*T_TOKENS];
__device__ int    g_tp[2*T_TOKENS];
__device__ float  g_tw[2*T_TOKENS];
// fp16 weights (single term)
__device__ __half g_wg[(size_t)WELEMS];
__device__ __half g_wu[(size_t)WELEMS];
__device__ __half g_wd[(size_t)WELEMS];

// ---------------- helpers ----------------
__device__ __forceinline__ uint32_t smem_u32(const void* p) {
    uint32_t a;
    asm("{ .reg .u64 t; cvta.to.shared.u64 t, %1; cvt.u32.u64 %0, t; }" : "=r"(a) : "l"(p));
    return a;
}
__device__ __forceinline__ void ldsm_x4(uint32_t* r, uint32_t addr) {
    asm volatile("ldmatrix.sync.aligned.m8n8.x4.shared.b16 {%0,%1,%2,%3}, [%4];"
        : "=r"(r[0]), "=r"(r[1]), "=r"(r[2]), "=r"(r[3]) : "r"(addr));
}
__device__ __forceinline__ void mma_fp16(float* c, const uint32_t* a, const uint32_t* b) {
    asm volatile(
        "mma.sync.aligned.m16n8k16.row.col.f32.f16.f16.f32 "
        "{%0,%1,%2,%3}, {%4,%5,%6,%7}, {%8,%9}, {%0,%1,%2,%3};"
        : "+f"(c[0]), "+f"(c[1]), "+f"(c[2]), "+f"(c[3])
        : "r"(a[0]), "r"(a[1]), "r"(a[2]), "r"(a[3]), "r"(b[0]), "r"(b[1]));
}
__device__ __forceinline__ void cp16(uint32_t dst, const void* src, uint32_t sz) {
    asm volatile("cp.async.cg.shared.global [%0], [%1], 16, %2;"
        :: "r"(dst), "l"(src), "r"(sz) : "memory");
}
#define CP_COMMIT() asm volatile("cp.async.commit_group;" ::: "memory")
template<int N> __device__ __forceinline__ void cp_wait() {
    asm volatile("cp.async.wait_group %0;" :: "n"(N) : "memory");
}
__device__ __forceinline__ uint32_t packh2(__half a, __half b) {
    __half2 v = __halves2half2(a, b);
    return *reinterpret_cast<uint32_t*>(&v);
}
__device__ __forceinline__ float warp_sum(float v) {
#pragma unroll
    for (int o = 16; o > 0; o >>= 1)
        v += __shfl_xor_sync(0xFFFFFFFFu, v, o);
    return v;
}

// ---------------------------------------------------------------------------
__global__ void reset_kernel() {
    if (threadIdx.x < N_EXP) g_cnt[threadIdx.x] = 0;
}

// ---------------------------------------------------------------------------
// Fused prep kernel: router blocks + weight-cast blocks.
__global__ __launch_bounds__(256) void prep_kernel(
    const float* __restrict__ hs,
    const float* __restrict__ rmsw,
    const float* __restrict__ rw,
    const float* __restrict__ wg,
    const float* __restrict__ wu,
    const float* __restrict__ wd,
    float* __restrict__ out_logits)
{
    const int tid = threadIdx.x;

    if (blockIdx.x >= T_TOKENS) {
        int sb = blockIdx.x - T_TOKENS;
        int w = sb / SPLIT_BLOCKS;
        int i = (sb - w * SPLIT_BLOCKS) * 256 + tid;
        if (i >= SPLIT_N4) return;
        const float* src = (w == 0) ? wg : (w == 1) ? wu : wd;
        __half* hi = (w == 0) ? g_wg : (w == 1) ? g_wu : g_wd;
        float4 v = ((const float4*)src)[i];
        ((uint2*)hi)[i] = make_uint2(
            packh2(__float2half_rn(v.x), __float2half_rn(v.y)),
            packh2(__float2half_rn(v.z), __float2half_rn(v.w)));
        return;
    }

    const int t    = blockIdx.x;
    const int wid  = tid >> 5;
    const int lane = tid & 31;
    const float* x = hs + (size_t)t * H_DIM;

    __shared__ float swred[8];
    __shared__ float sacc[8][N_EXP];
    __shared__ float s_scale;
    __shared__ float slog[N_EXP];

    float ss = 0.f;
    for (int i = tid; i < H_DIM; i += 256) { float v = x[i]; ss += v * v; }
    ss = warp_sum(ss);
    if (lane == 0) swred[wid] = ss;
    __syncthreads();
    if (tid == 0) {
        float tot = 0.f;
#pragma unroll
        for (int w = 0; w < 8; w++) tot += swred[w];
        s_scale = rsqrtf(tot / (float)H_DIM + 1e-6f);
    }
    __syncthreads();
    const float scale = s_scale;

    float acc[N_EXP];
#pragma unroll
    for (int e = 0; e < N_EXP; e++) acc[e] = 0.f;
    for (int i = tid; i < H_DIM; i += 256) {
        float v = x[i] * scale * rmsw[i];
        g_xn[(size_t)t * H_DIM + i] = __float2half_rn(v);
#pragma unroll
        for (int e = 0; e < N_EXP; e++) acc[e] += v * rw[e * H_DIM + i];
    }
#pragma unroll
    for (int e = 0; e < N_EXP; e++) {
        float v = warp_sum(acc[e]);
        if (lane == 0) sacc[wid][e] = v;
    }
    __syncthreads();
    if (tid < N_EXP) {
        float tot = 0.f;
#pragma unroll
        for (int w = 0; w < 8; w++) tot += sacc[w][tid];
        slog[tid] = tot;
    }
    __syncthreads();

    if (tid == 0) {
        float l[N_EXP], m = -1e30f;
#pragma unroll
        for (int e = 0; e < N_EXP; e++) {
            l[e] = slog[e];
            out_logits[(size_t)t * N_EXP + e] = l[e];
            m = fmaxf(m, l[e]);
        }
        float p[N_EXP], s = 0.f;
#pragma unroll
        for (int e = 0; e < N_EXP; e++) { p[e] = expf(l[e] - m); s += p[e]; }
#pragma unroll
        for (int e = 0; e < N_EXP; e++) p[e] /= s;

        int a = 0;
#pragma unroll
        for (int e = 1; e < N_EXP; e++) if (p[e] > p[a]) a = e;
        int b = (a == 0) ? 1 : 0;
#pragma unroll
        for (int e = 0; e < N_EXP; e++) if (e != a && p[e] > p[b]) b = e;

        float wsum = p[a] + p[b] + 1e-20f;
        float wa = p[a] / wsum, wb = p[b] / wsum;

        int pa = atomicAdd(&g_cnt[a], 1);
        g_tok[a * MAXTOK + pa] = t;
        g_te[2*t] = a; g_tp[2*t] = pa; g_tw[2*t] = wa;
        int pb = atomicAdd(&g_cnt[b], 1);
        g_tok[b * MAXTOK + pb] = t;
        g_te[2*t+1] = b; g_tp[2*t+1] = pb; g_tw[2*t+1] = wb;
    }
}

// ---------------------------------------------------------------------------
__global__ void offsets_kernel() {
    int run = 0;
    for (int e = 0; e < N_EXP; e++) { g_off[e] = run; run += g_cnt[e]; }
}

// ---------------------------------------------------------------------------
// fp16 HMMA GEMMs (single term), 3-stage cp.async pipeline, ONE sync per K-tile.
// Block tile 128(M) x 64(N), K-tile 64, 256 threads, warp grid 4x2 (warp 32x32),
// 2 CTAs/SM.
#define AS 72
#define G1_STG_E (256*AS)                  // halves per stage = 18432
#define G1_STG_B (G1_STG_E*2)              // 36864 B
#define G1_SMEM  (3*G1_STG_B)              // 110592 B
#define G2_STG_E (192*AS)                  // 13824
#define G2_STG_B (G2_STG_E*2)              // 27648 B
#define G2_SMEM  (3*G2_STG_B)              // 82944 B

__global__ __launch_bounds__(256, 2) void gemm1_kernel()
{
    const int e  = blockIdx.z;
    const int mt = blockIdx.y;
    const int nt = blockIdx.x;
    const int cnt = g_cnt[e];
    if (mt * 128 >= cnt) return;
    const int tid = threadIdx.x;
    const int wid = tid >> 5;
    const int lane = tid & 31;

    extern __shared__ __half sm[];
    __shared__ int stok[128];

    if (tid < 128) {
        int row = mt * 128 + tid;
        stok[tid] = (row < cnt) ? g_tok[e * MAXTOK + row] : -1;
    }
    __syncthreads();

    const size_t wbase = (size_t)e * I_DIM * H_DIM + (size_t)(nt * 64) * H_DIM;
    const __half* wgp = g_wg + wbase;
    const __half* wup = g_wu + wbase;

    const uint32_t smb = smem_u32(sm);

    // hoisted per-thread load coordinates
    const __half* aSrc[4]; uint32_t aDst[4], aSz[4];
#pragma unroll
    for (int p = 0; p < 4; p++) {
        int q = tid + p * 256;
        int r = q >> 3, c8 = (q & 7) * 8;
        int tok = stok[r];
        aSz[p]  = tok >= 0 ? 16u : 0u;
        aSrc[p] = g_xn + (size_t)(tok < 0 ? 0 : tok) * H_DIM + c8;
        aDst[p] = (uint32_t)(r * AS + c8) * 2u;
    }
    size_t bOfs[2]; uint32_t bDst[2];
#pragma unroll
    for (int p = 0; p < 2; p++) {
        int q = tid + p * 256;
        int n = q >> 3, c8 = (q & 7) * 8;
        bOfs[p] = (size_t)n * H_DIM + c8;
        bDst[p] = (uint32_t)(n * AS + c8) * 2u;
    }

#define G1_LOAD(S, KK) do {                                                     \
    uint32_t sb = smb + (uint32_t)(S) * G1_STG_B;                               \
    _Pragma("unroll")                                                           \
    for (int p = 0; p < 4; p++)                                                 \
        cp16(sb + aDst[p], aSrc[p] + (KK), aSz[p]);                             \
    _Pragma("unroll")                                                           \
    for (int p = 0; p < 2; p++) {                                               \
        size_t o = bOfs[p] + (KK);                                              \
        cp16(sb + 128*AS*2 + bDst[p], wgp + o, 16u);                            \
        cp16(sb + 192*AS*2 + bDst[p], wup + o, 16u);                            \
    }                                                                           \
} while (0)

    float cg[2][4][4], cu[2][4][4];
#pragma unroll
    for (int i = 0; i < 2; i++)
#pragma unroll
        for (int j = 0; j < 4; j++)
#pragma unroll
            for (int k = 0; k < 4; k++) { cg[i][j][k] = 0.f; cu[i][j][k] = 0.f; }

    const int wm = wid >> 1;
    const int wn = wid & 1;
    const int lr = lane & 15;
    const int lc = (lane >> 4) * 8;

    G1_LOAD(0, 0);
    CP_COMMIT();
    G1_LOAD(1, 64);
    CP_COMMIT();

    const int KT = H_DIM / 64;
    int cur = 0, nxt = 2;
#pragma unroll 3
    for (int kt = 0; kt < KT; kt++) {
        if (kt + 1 < KT) cp_wait<1>(); else cp_wait<0>();
        __syncthreads();
        // safe to overwrite stage `nxt` (= stage of kt-1): all warps passed the
        // barrier, so all finished iteration kt-1's reads of it.
        if (kt + 2 < KT) {
            G1_LOAD(nxt, (kt + 2) * 64);
            CP_COMMIT();
        }

        const __half* Ah = sm + cur * G1_STG_E;
        const __half* Bg = Ah + 128*AS;
        const __half* Bu = Ah + 192*AS;

#pragma unroll
        for (int ks = 0; ks < 4; ks++) {
            uint32_t ah[2][4];
#pragma unroll
            for (int mf = 0; mf < 2; mf++) {
                int so = (wm*32 + mf*16 + lr) * AS + ks*16 + lc;
                ldsm_x4(ah[mf], smem_u32(Ah + so));
            }
            uint32_t bg[2][4], bu[2][4];
#pragma unroll
            for (int n2 = 0; n2 < 2; n2++) {
                int so = (wn*32 + n2*16 + lr) * AS + ks*16 + lc;
                ldsm_x4(bg[n2], smem_u32(Bg + so));
                ldsm_x4(bu[n2], smem_u32(Bu + so));
            }
#pragma unroll
            for (int mf = 0; mf < 2; mf++)
#pragma unroll
            for (int nf = 0; nf < 4; nf++) {
                int n2 = nf >> 1, nh = nf & 1;
                uint32_t bG[2] = { bg[n2][nh], bg[n2][nh+2] };
                uint32_t bU[2] = { bu[n2][nh], bu[n2][nh+2] };
                mma_fp16(cg[mf][nf], ah[mf], bG);
                mma_fp16(cu[mf][nf], ah[mf], bU);
            }
        }
        cur = (cur == 2) ? 0 : cur + 1;
        nxt = (nxt == 2) ? 0 : nxt + 1;
    }
#undef G1_LOAD

    const int off = g_off[e];
#pragma unroll
    for (int mf = 0; mf < 2; mf++)
#pragma unroll
    for (int nf = 0; nf < 4; nf++) {
        int col = nt*64 + wn*32 + nf*8 + (lane & 3)*2;
#pragma unroll
        for (int half = 0; half < 2; half++) {
            int row = mt*128 + wm*32 + mf*16 + (lane >> 2) + half*8;
            if (row < cnt) {
                float g0 = cg[mf][nf][half*2],   g1 = cg[mf][nf][half*2+1];
                float u0 = cu[mf][nf][half*2],   u1 = cu[mf][nf][half*2+1];
                float h0 = (g0 / (1.f + expf(-g0))) * u0;
                float h1 = (g1 / (1.f + expf(-g1))) * u1;
                size_t base = (size_t)(off + row) * I_DIM + col;
                *(uint32_t*)(g_h + base) = packh2(__float2half_rn(h0), __float2half_rn(h1));
            }
        }
    }
}

// ---------------------------------------------------------------------------
__global__ __launch_bounds__(256, 2) void gemm2_kernel()
{
    const int e  = blockIdx.z;
    const int mt = blockIdx.y;
    const int nt = blockIdx.x;
    const int cnt = g_cnt[e];
    if (mt * 128 >= cnt) return;
    const int tid = threadIdx.x;
    const int wid = tid >> 5;
    const int lane = tid & 31;
    const int off = g_off[e];

    extern __shared__ __half sm[];

    const size_t wbase = (size_t)e * H_DIM * I_DIM + (size_t)(nt * 64) * I_DIM;
    const __half* wdp = g_wd + wbase;

    const uint32_t smb = smem_u32(sm);

    const __half* aSrc[4]; uint32_t aDst[4];
#pragma unroll
    for (int p = 0; p < 4; p++) {
        int q = tid + p * 256;
        int r = q >> 3, c8 = (q & 7) * 8;
        aSrc[p] = g_h + (size_t)(off + mt*128 + r) * I_DIM + c8;
        aDst[p] = (uint32_t)(r * AS + c8) * 2u;
    }
    size_t bOfs[2]; uint32_t bDst[2];
#pragma unroll
    for (int p = 0; p < 2; p++) {
        int q = tid + p * 256;
        int n = q >> 3, c8 = (q & 7) * 8;
        bOfs[p] = (size_t)n * I_DIM + c8;
        bDst[p] = (uint32_t)(n * AS + c8) * 2u;
    }

#define G2_LOAD(S, KK) do {                                                     \
    uint32_t sb = smb + (uint32_t)(S) * G2_STG_B;                               \
    _Pragma("unroll")                                                           \
    for (int p = 0; p < 4; p++)                                                 \
        cp16(sb + aDst[p], aSrc[p] + (KK), 16u);                                \
    _Pragma("unroll")                                                           \
    for (int p = 0; p < 2; p++)                                                 \
        cp16(sb + 128*AS*2 + bDst[p], wdp + bOfs[p] + (KK), 16u);               \
} while (0)

    float cc[2][4][4];
#pragma unroll
    for (int i = 0; i < 2; i++)
#pragma unroll
        for (int j = 0; j < 4; j++)
#pragma unroll
            for (int k = 0; k < 4; k++) cc[i][j][k] = 0.f;

    const int wm = wid >> 1;
    const int wn = wid & 1;
    const int lr = lane & 15;
    const int lc = (lane >> 4) * 8;

    G2_LOAD(0, 0);
    CP_COMMIT();
    G2_LOAD(1, 64);
    CP_COMMIT();

    const int KT = I_DIM / 64;
    int cur = 0, nxt = 2;
#pragma unroll 3
    for (int kt = 0; kt < KT; kt++) {
        if (kt + 1 < KT) cp_wait<1>(); else cp_wait<0>();
        __syncthreads();
        if (kt + 2 < KT) {
            G2_LOAD(nxt, (kt + 2) * 64);
            CP_COMMIT();
        }

        const __half* Ah = sm + cur * G2_STG_E;
        const __half* Bd = Ah + 128*AS;

#pragma unroll
        for (int ks = 0; ks < 4; ks++) {
            uint32_t ah[2][4];
#pragma unroll
            for (int mf = 0; mf < 2; mf++) {
                int so = (wm*32 + mf*16 + lr) * AS + ks*16 + lc;
                ldsm_x4(ah[mf], smem_u32(Ah + so));
            }
            uint32_t bd[2][4];
#pragma unroll
            for (int n2 = 0; n2 < 2; n2++) {
                int so = (wn*32 + n2*16 + lr) * AS + ks*16 + lc;
                ldsm_x4(bd[n2], smem_u32(Bd + so));
            }
#pragma unroll
            for (int mf = 0; mf < 2; mf++)
#pragma unroll
            for (int nf = 0; nf < 4; nf++) {
                int n2 = nf >> 1, nh = nf & 1;
                uint32_t bB[2] = { bd[n2][nh], bd[n2][nh+2] };
                mma_fp16(cc[mf][nf], ah[mf], bB);
            }
        }
        cur = (cur == 2) ? 0 : cur + 1;
        nxt = (nxt == 2) ? 0 : nxt + 1;
    }
#undef G2_LOAD

#pragma unroll
    for (int mf = 0; mf < 2; mf++)
#pragma unroll
    for (int nf = 0; nf < 4; nf++) {
        int col = nt*64 + wn*32 + nf*8 + (lane & 3)*2;
#pragma unroll
        for (int half = 0; half < 2; half++) {
            int row = mt*128 + wm*32 + mf*16 + (lane >> 2) + half*8;
            if (row < cnt) {
                float2 v = make_float2(cc[mf][nf][half*2], cc[mf][nf][half*2+1]);
                *(float2*)(g_y + (size_t)(off + row) * H_DIM + col) = v;
            }
        }
    }
}

// ---------------------------------------------------------------------------
__global__ __launch_bounds__(256) void combine_kernel(float* __restrict__ out)
{
    const int t = blockIdx.x;
    const int tid = threadIdx.x;
    const int e0 = g_te[2*t],   p0 = g_tp[2*t];
    const int e1 = g_te[2*t+1], p1 = g_tp[2*t+1];
    const float w0 = g_tw[2*t], w1 = g_tw[2*t+1];
    const float* y0 = g_y + (size_t)(g_off[e0] + p0) * H_DIM;
    const float* y1 = g_y + (size_t)(g_off[e1] + p1) * H_DIM;
    float* o = out + (size_t)t * H_DIM;
#pragma unroll
    for (int it = 0; it < 2; it++) {
        int i = (tid + it * 256) * 4;
        float4 a = *(const float4*)(y0 + i);
        float4 b = *(const float4*)(y1 + i);
        float4 r;
        r.x = w0 * a.x + w1 * b.x;
        r.y = w0 * a.y + w1 * b.y;
        r.z = w0 * a.z + w1 * b.z;
        r.w = w0 * a.w + w1 * b.w;
        *(float4*)(o + i) = r;
    }
}

// ---------------------------------------------------------------------------
extern "C" void kernel_launch(void* const* d_in, const int* in_sizes, int n_in,
                              void* d_out, int out_size)
{
    const float* hs   = (const float*)d_in[0];
    const float* rmsw = (const float*)d_in[1];
    const float* rw   = (const float*)d_in[2];
    const float* wg   = (const float*)d_in[3];
    const float* wu   = (const float*)d_in[4];
    const float* wd   = (const float*)d_in[5];

    float* out        = (float*)d_out;
    float* out_logits = (float*)d_out + (size_t)T_TOKENS * H_DIM;

    cudaFuncSetAttribute(gemm1_kernel, cudaFuncAttributeMaxDynamicSharedMemorySize, G1_SMEM);
    cudaFuncSetAttribute(gemm2_kernel, cudaFuncAttributeMaxDynamicSharedMemorySize, G2_SMEM);

    reset_kernel<<<1, 32>>>();

    int grid = T_TOKENS + 3 * SPLIT_BLOCKS;
    prep_kernel<<<grid, 256>>>(hs, rmsw, rw, wg, wu, wd, out_logits);

    offsets_kernel<<<1, 1>>>();

    dim3 g1(I_DIM / 64, T_TOKENS / 128, N_EXP);   // 22 x 64 x 8
    gemm1_kernel<<<g1, 256, G1_SMEM>>>();

    dim3 g2(H_DIM / 64, T_TOKENS / 128, N_EXP);   // 32 x 64 x 8
    gemm2_kernel<<<g2, 256, G2_SMEM>>>();

    combine_kernel<<<T_TOKENS, 256>>>(out);
}

// round 12
// speedup vs baseline: 2.5796x; 1.0437x over previous
#include <cuda_runtime.h>
#include <cuda_fp16.h>
#include <math.h>
#include <stdint.h>

#define T_TOKENS 8192
#define H_DIM    2048
#define I_DIM    1408
#define N_EXP    8
#define MAXTOK   8192
#define TOTROWS  (2*T_TOKENS)
#define WELEMS   (N_EXP * I_DIM * H_DIM)
#define SPLIT_N4 (WELEMS / 4)
#define SPLIT_BLOCKS ((SPLIT_N4 + 255) / 256)

// ---------------- scratch (static device globals) ----------------
__device__ __half g_xn[(size_t)T_TOKENS*H_DIM];
__device__ __half g_h [(size_t)(TOTROWS+128)*I_DIM];
__device__ float  g_y [(size_t)TOTROWS*H_DIM];
__device__ int    g_cnt[N_EXP];
__device__ int    g_off[N_EXP];
__device__ int    g_tok[N_EXP*MAXTOK];
__device__ int    g_te[2*T_TOKENS];
__device__ int    g_tp[2*T_TOKENS];
__device__ float  g_tw[2*T_TOKENS];
// fp16 weights (single term)
__device__ __half g_wg[(size_t)WELEMS];
__device__ __half g_wu[(size_t)WELEMS];
__device__ __half g_wd[(size_t)WELEMS];

// ---------------- helpers ----------------
__device__ __forceinline__ uint32_t smem_u32(const void* p) {
    uint32_t a;
    asm("{ .reg .u64 t; cvta.to.shared.u64 t, %1; cvt.u32.u64 %0, t; }" : "=r"(a) : "l"(p));
    return a;
}
__device__ __forceinline__ void ldsm_x4(uint32_t* r, uint32_t addr) {
    asm volatile("ldmatrix.sync.aligned.m8n8.x4.shared.b16 {%0,%1,%2,%3}, [%4];"
        : "=r"(r[0]), "=r"(r[1]), "=r"(r[2]), "=r"(r[3]) : "r"(addr));
}
__device__ __forceinline__ void mma_fp16(float* c, const uint32_t* a, const uint32_t* b) {
    asm volatile(
        "mma.sync.aligned.m16n8k16.row.col.f32.f16.f16.f32 "
        "{%0,%1,%2,%3}, {%4,%5,%6,%7}, {%8,%9}, {%0,%1,%2,%3};"
        : "+f"(c[0]), "+f"(c[1]), "+f"(c[2]), "+f"(c[3])
        : "r"(a[0]), "r"(a[1]), "r"(a[2]), "r"(a[3]), "r"(b[0]), "r"(b[1]));
}
__device__ __forceinline__ void cp16(uint32_t dst, const void* src, uint32_t sz) {
    asm volatile("cp.async.cg.shared.global [%0], [%1], 16, %2;"
        :: "r"(dst), "l"(src), "r"(sz) : "memory");
}
#define CP_COMMIT() asm volatile("cp.async.commit_group;" ::: "memory")
template<int N> __device__ __forceinline__ void cp_wait() {
    asm volatile("cp.async.wait_group %0;" :: "n"(N) : "memory");
}
__device__ __forceinline__ uint32_t packh2(__half a, __half b) {
    __half2 v = __halves2half2(a, b);
    return *reinterpret_cast<uint32_t*>(&v);
}
__device__ __forceinline__ float warp_sum(float v) {
#pragma unroll
    for (int o = 16; o > 0; o >>= 1)
        v += __shfl_xor_sync(0xFFFFFFFFu, v, o);
    return v;
}

// ---------------------------------------------------------------------------
__global__ void reset_kernel() {
    if (threadIdx.x < N_EXP) g_cnt[threadIdx.x] = 0;
}

// ---------------------------------------------------------------------------
// Fused prep kernel: router blocks + weight-cast blocks.
__global__ __launch_bounds__(256) void prep_kernel(
    const float* __restrict__ hs,
    const float* __restrict__ rmsw,
    const float* __restrict__ rw,
    const float* __restrict__ wg,
    const float* __restrict__ wu,
    const float* __restrict__ wd,
    float* __restrict__ out_logits)
{
    const int tid = threadIdx.x;

    if (blockIdx.x >= T_TOKENS) {
        int sb = blockIdx.x - T_TOKENS;
        int w = sb / SPLIT_BLOCKS;
        int i = (sb - w * SPLIT_BLOCKS) * 256 + tid;
        if (i >= SPLIT_N4) return;
        const float* src = (w == 0) ? wg : (w == 1) ? wu : wd;
        __half* hi = (w == 0) ? g_wg : (w == 1) ? g_wu : g_wd;
        float4 v = ((const float4*)src)[i];
        ((uint2*)hi)[i] = make_uint2(
            packh2(__float2half_rn(v.x), __float2half_rn(v.y)),
            packh2(__float2half_rn(v.z), __float2half_rn(v.w)));
        return;
    }

    const int t    = blockIdx.x;
    const int wid  = tid >> 5;
    const int lane = tid & 31;
    const float* x = hs + (size_t)t * H_DIM;

    __shared__ float swred[8];
    __shared__ float sacc[8][N_EXP];
    __shared__ float s_scale;
    __shared__ float slog[N_EXP];

    float ss = 0.f;
    for (int i = tid; i < H_DIM; i += 256) { float v = x[i]; ss += v * v; }
    ss = warp_sum(ss);
    if (lane == 0) swred[wid] = ss;
    __syncthreads();
    if (tid == 0) {
        float tot = 0.f;
#pragma unroll
        for (int w = 0; w < 8; w++) tot += swred[w];
        s_scale = rsqrtf(tot / (float)H_DIM + 1e-6f);
    }
    __syncthreads();
    const float scale = s_scale;

    float acc[N_EXP];
#pragma unroll
    for (int e = 0; e < N_EXP; e++) acc[e] = 0.f;
    for (int i = tid; i < H_DIM; i += 256) {
        float v = x[i] * scale * rmsw[i];
        g_xn[(size_t)t * H_DIM + i] = __float2half_rn(v);
#pragma unroll
        for (int e = 0; e < N_EXP; e++) acc[e] += v * rw[e * H_DIM + i];
    }
#pragma unroll
    for (int e = 0; e < N_EXP; e++) {
        float v = warp_sum(acc[e]);
        if (lane == 0) sacc[wid][e] = v;
    }
    __syncthreads();
    if (tid < N_EXP) {
        float tot = 0.f;
#pragma unroll
        for (int w = 0; w < 8; w++) tot += sacc[w][tid];
        slog[tid] = tot;
    }
    __syncthreads();

    if (tid == 0) {
        float l[N_EXP], m = -1e30f;
#pragma unroll
        for (int e = 0; e < N_EXP; e++) {
            l[e] = slog[e];
            out_logits[(size_t)t * N_EXP + e] = l[e];
            m = fmaxf(m, l[e]);
        }
        float p[N_EXP], s = 0.f;
#pragma unroll
        for (int e = 0; e < N_EXP; e++) { p[e] = expf(l[e] - m); s += p[e]; }
#pragma unroll
        for (int e = 0; e < N_EXP; e++) p[e] /= s;

        int a = 0;
#pragma unroll
        for (int e = 1; e < N_EXP; e++) if (p[e] > p[a]) a = e;
        int b = (a == 0) ? 1 : 0;
#pragma unroll
        for (int e = 0; e < N_EXP; e++) if (e != a && p[e] > p[b]) b = e;

        float wsum = p[a] + p[b] + 1e-20f;
        float wa = p[a] / wsum, wb = p[b] / wsum;

        int pa = atomicAdd(&g_cnt[a], 1);
        g_tok[a * MAXTOK + pa] = t;
        g_te[2*t] = a; g_tp[2*t] = pa; g_tw[2*t] = wa;
        int pb = atomicAdd(&g_cnt[b], 1);
        g_tok[b * MAXTOK + pb] = t;
        g_te[2*t+1] = b; g_tp[2*t+1] = pb; g_tw[2*t+1] = wb;
    }
}

// ---------------------------------------------------------------------------
__global__ void offsets_kernel() {
    int run = 0;
    for (int e = 0; e < N_EXP; e++) { g_off[e] = run; run += g_cnt[e]; }
}

// ---------------------------------------------------------------------------
// fp16 HMMA GEMMs, 3-stage cp.async pipeline, one sync per K-tile.
// Block tile 128(M) x 64(N), K-tile 64, 256 threads, warp grid 4x2 (warp 32x32),
// 2 CTAs/SM. LDSM addresses fully precomputed in u32 (no cvta in hot loop).
#define AS 72
#define G1_STG_E (256*AS)                  // halves per stage = 18432
#define G1_STG_B (G1_STG_E*2)              // 36864 B
#define G1_SMEM  (3*G1_STG_B)              // 110592 B
#define G2_STG_E (192*AS)                  // 13824
#define G2_STG_B (G2_STG_E*2)              // 27648 B
#define G2_SMEM  (3*G2_STG_B)              // 82944 B

__global__ __launch_bounds__(256, 2) void gemm1_kernel()
{
    const int e  = blockIdx.z;
    const int mt = blockIdx.y;
    const int nt = blockIdx.x;
    const int cnt = g_cnt[e];
    if (mt * 128 >= cnt) return;
    const int tid = threadIdx.x;
    const int wid = tid >> 5;
    const int lane = tid & 31;

    extern __shared__ __half sm[];
    __shared__ int stok[128];

    if (tid < 128) {
        int row = mt * 128 + tid;
        stok[tid] = (row < cnt) ? g_tok[e * MAXTOK + row] : -1;
    }
    __syncthreads();

    const size_t wbase = (size_t)e * I_DIM * H_DIM + (size_t)(nt * 64) * H_DIM;
    const __half* wgp = g_wg + wbase;
    const __half* wup = g_wu + wbase;

    const uint32_t smb = smem_u32(sm);

    // hoisted per-thread cp.async coordinates
    const __half* aSrc[4]; uint32_t aDst[4], aSz[4];
#pragma unroll
    for (int p = 0; p < 4; p++) {
        int q = tid + p * 256;
        int r = q >> 3, c8 = (q & 7) * 8;
        int tok = stok[r];
        aSz[p]  = tok >= 0 ? 16u : 0u;
        aSrc[p] = g_xn + (size_t)(tok < 0 ? 0 : tok) * H_DIM + c8;
        aDst[p] = smb + (uint32_t)(r * AS + c8) * 2u;
    }
    size_t bOfs[2]; uint32_t bDst[2];
#pragma unroll
    for (int p = 0; p < 2; p++) {
        int q = tid + p * 256;
        int n = q >> 3, c8 = (q & 7) * 8;
        bOfs[p] = (size_t)n * H_DIM + c8;
        bDst[p] = smb + (uint32_t)(n * AS + c8) * 2u;
    }

#define G1_LOAD(S, KK) do {                                                     \
    uint32_t so = (uint32_t)(S) * G1_STG_B;                                     \
    _Pragma("unroll")                                                           \
    for (int p = 0; p < 4; p++)                                                 \
        cp16(aDst[p] + so, aSrc[p] + (KK), aSz[p]);                             \
    _Pragma("unroll")                                                           \
    for (int p = 0; p < 2; p++) {                                               \
        size_t o = bOfs[p] + (KK);                                              \
        cp16(bDst[p] + so + 128*AS*2, wgp + o, 16u);                            \
        cp16(bDst[p] + so + 192*AS*2, wup + o, 16u);                            \
    }                                                                           \
} while (0)

    float cg[2][4][4], cu[2][4][4];
#pragma unroll
    for (int i = 0; i < 2; i++)
#pragma unroll
        for (int j = 0; j < 4; j++)
#pragma unroll
            for (int k = 0; k < 4; k++) { cg[i][j][k] = 0.f; cu[i][j][k] = 0.f; }

    const int wm = wid >> 1;
    const int wn = wid & 1;
    const int lr = lane & 15;
    const int lc = (lane >> 4) * 8;

    // precomputed u32 LDSM base addresses (stage 0); all loop offsets are
    // compile-time constants under the unrolled stage index.
    const uint32_t aB  = smb + (uint32_t)(((wm*32 + lr) * AS + lc) * 2);
    const uint32_t bgB = smb + (uint32_t)((128*AS + (wn*32 + lr) * AS + lc) * 2);
    const uint32_t buB = bgB + 64*AS*2;

    G1_LOAD(0, 0);
    CP_COMMIT();
    G1_LOAD(1, 64);
    CP_COMMIT();

    const int KT = H_DIM / 64;
    int cur = 0, nxt = 2;
#pragma unroll 3
    for (int kt = 0; kt < KT; kt++) {
        if (kt + 1 < KT) cp_wait<1>(); else cp_wait<0>();
        __syncthreads();
        if (kt + 2 < KT) {
            G1_LOAD(nxt, (kt + 2) * 64);
            CP_COMMIT();
        }

        const uint32_t so = (uint32_t)cur * G1_STG_B;

#pragma unroll
        for (int ks = 0; ks < 4; ks++) {
            uint32_t ah[2][4];
#pragma unroll
            for (int mf = 0; mf < 2; mf++)
                ldsm_x4(ah[mf], aB + so + (uint32_t)((mf*16*AS + ks*16) * 2));
            uint32_t bg[2][4], bu[2][4];
#pragma unroll
            for (int n2 = 0; n2 < 2; n2++) {
                uint32_t fo = (uint32_t)((n2*16*AS + ks*16) * 2);
                ldsm_x4(bg[n2], bgB + so + fo);
                ldsm_x4(bu[n2], buB + so + fo);
            }
#pragma unroll
            for (int mf = 0; mf < 2; mf++)
#pragma unroll
            for (int nf = 0; nf < 4; nf++) {
                int n2 = nf >> 1, nh = nf & 1;
                uint32_t bG[2] = { bg[n2][nh], bg[n2][nh+2] };
                uint32_t bU[2] = { bu[n2][nh], bu[n2][nh+2] };
                mma_fp16(cg[mf][nf], ah[mf], bG);
                mma_fp16(cu[mf][nf], ah[mf], bU);
            }
        }
        cur = (cur == 2) ? 0 : cur + 1;
        nxt = (nxt == 2) ? 0 : nxt + 1;
    }
#undef G1_LOAD

    const int off = g_off[e];
#pragma unroll
    for (int mf = 0; mf < 2; mf++)
#pragma unroll
    for (int nf = 0; nf < 4; nf++) {
        int col = nt*64 + wn*32 + nf*8 + (lane & 3)*2;
#pragma unroll
        for (int half = 0; half < 2; half++) {
            int row = mt*128 + wm*32 + mf*16 + (lane >> 2) + half*8;
            if (row < cnt) {
                float g0 = cg[mf][nf][half*2],   g1 = cg[mf][nf][half*2+1];
                float u0 = cu[mf][nf][half*2],   u1 = cu[mf][nf][half*2+1];
                float h0 = (g0 / (1.f + expf(-g0))) * u0;
                float h1 = (g1 / (1.f + expf(-g1))) * u1;
                size_t base = (size_t)(off + row) * I_DIM + col;
                *(uint32_t*)(g_h + base) = packh2(__float2half_rn(h0), __float2half_rn(h1));
            }
        }
    }
}

// ---------------------------------------------------------------------------
__global__ __launch_bounds__(256, 2) void gemm2_kernel()
{
    const int e  = blockIdx.z;
    const int mt = blockIdx.y;
    const int nt = blockIdx.x;
    const int cnt = g_cnt[e];
    if (mt * 128 >= cnt) return;
    const int tid = threadIdx.x;
    const int wid = tid >> 5;
    const int lane = tid & 31;
    const int off = g_off[e];

    extern __shared__ __half sm[];

    const size_t wbase = (size_t)e * H_DIM * I_DIM + (size_t)(nt * 64) * I_DIM;
    const __half* wdp = g_wd + wbase;

    const uint32_t smb = smem_u32(sm);

    const __half* aSrc[4]; uint32_t aDst[4];
#pragma unroll
    for (int p = 0; p < 4; p++) {
        int q = tid + p * 256;
        int r = q >> 3, c8 = (q & 7) * 8;
        aSrc[p] = g_h + (size_t)(off + mt*128 + r) * I_DIM + c8;
        aDst[p] = smb + (uint32_t)(r * AS + c8) * 2u;
    }
    size_t bOfs[2]; uint32_t bDst[2];
#pragma unroll
    for (int p = 0; p < 2; p++) {
        int q = tid + p * 256;
        int n = q >> 3, c8 = (q & 7) * 8;
        bOfs[p] = (size_t)n * I_DIM + c8;
        bDst[p] = smb + (uint32_t)(n * AS + c8) * 2u;
    }

#define G2_LOAD(S, KK) do {                                                     \
    uint32_t so = (uint32_t)(S) * G2_STG_B;                                     \
    _Pragma("unroll")                                                           \
    for (int p = 0; p < 4; p++)                                                 \
        cp16(aDst[p] + so, aSrc[p] + (KK), 16u);                                \
    _Pragma("unroll")                                                           \
    for (int p = 0; p < 2; p++)                                                 \
        cp16(bDst[p] + so + 128*AS*2, wdp + bOfs[p] + (KK), 16u);               \
} while (0)

    float cc[2][4][4];
#pragma unroll
    for (int i = 0; i < 2; i++)
#pragma unroll
        for (int j = 0; j < 4; j++)
#pragma unroll
            for (int k = 0; k < 4; k++) cc[i][j][k] = 0.f;

    const int wm = wid >> 1;
    const int wn = wid & 1;
    const int lr = lane & 15;
    const int lc = (lane >> 4) * 8;

    const uint32_t aB  = smb + (uint32_t)(((wm*32 + lr) * AS + lc) * 2);
    const uint32_t bdB = smb + (uint32_t)((128*AS + (wn*32 + lr) * AS + lc) * 2);

    G2_LOAD(0, 0);
    CP_COMMIT();
    G2_LOAD(1, 64);
    CP_COMMIT();

    const int KT = I_DIM / 64;
    int cur = 0, nxt = 2;
#pragma unroll 3
    for (int kt = 0; kt < KT; kt++) {
        if (kt + 1 < KT) cp_wait<1>(); else cp_wait<0>();
        __syncthreads();
        if (kt + 2 < KT) {
            G2_LOAD(nxt, (kt + 2) * 64);
            CP_COMMIT();
        }

        const uint32_t so = (uint32_t)cur * G2_STG_B;

#pragma unroll
        for (int ks = 0; ks < 4; ks++) {
            uint32_t ah[2][4];
#pragma unroll
            for (int mf = 0; mf < 2; mf++)
                ldsm_x4(ah[mf], aB + so + (uint32_t)((mf*16*AS + ks*16) * 2));
            uint32_t bd[2][4];
#pragma unroll
            for (int n2 = 0; n2 < 2; n2++)
                ldsm_x4(bd[n2], bdB + so + (uint32_t)((n2*16*AS + ks*16) * 2));
#pragma unroll
            for (int mf = 0; mf < 2; mf++)
#pragma unroll
            for (int nf = 0; nf < 4; nf++) {
                int n2 = nf >> 1, nh = nf & 1;
                uint32_t bB[2] = { bd[n2][nh], bd[n2][nh+2] };
                mma_fp16(cc[mf][nf], ah[mf], bB);
            }
        }
        cur = (cur == 2) ? 0 : cur + 1;
        nxt = (nxt == 2) ? 0 : nxt + 1;
    }
#undef G2_LOAD

#pragma unroll
    for (int mf = 0; mf < 2; mf++)
#pragma unroll
    for (int nf = 0; nf < 4; nf++) {
        int col = nt*64 + wn*32 + nf*8 + (lane & 3)*2;
#pragma unroll
        for (int half = 0; half < 2; half++) {
            int row = mt*128 + wm*32 + mf*16 + (lane >> 2) + half*8;
            if (row < cnt) {
                float2 v = make_float2(cc[mf][nf][half*2], cc[mf][nf][half*2+1]);
                *(float2*)(g_y + (size_t)(off + row) * H_DIM + col) = v;
            }
        }
    }
}

// ---------------------------------------------------------------------------
__global__ __launch_bounds__(256) void combine_kernel(float* __restrict__ out)
{
    const int t = blockIdx.x;
    const int tid = threadIdx.x;
    const int e0 = g_te[2*t],   p0 = g_tp[2*t];
    const int e1 = g_te[2*t+1], p1 = g_tp[2*t+1];
    const float w0 = g_tw[2*t], w1 = g_tw[2*t+1];
    const float* y0 = g_y + (size_t)(g_off[e0] + p0) * H_DIM;
    const float* y1 = g_y + (size_t)(g_off[e1] + p1) * H_DIM;
    float* o = out + (size_t)t * H_DIM;
#pragma unroll
    for (int it = 0; it < 2; it++) {
        int i = (tid + it * 256) * 4;
        float4 a = *(const float4*)(y0 + i);
        float4 b = *(const float4*)(y1 + i);
        float4 r;
        r.x = w0 * a.x + w1 * b.x;
        r.y = w0 * a.y + w1 * b.y;
        r.z = w0 * a.z + w1 * b.z;
        r.w = w0 * a.w + w1 * b.w;
        *(float4*)(o + i) = r;
    }
}

// ---------------------------------------------------------------------------
extern "C" void kernel_launch(void* const* d_in, const int* in_sizes, int n_in,
                              void* d_out, int out_size)
{
    const float* hs   = (const float*)d_in[0];
    const float* rmsw = (const float*)d_in[1];
    const float* rw   = (const float*)d_in[2];
    const float* wg   = (const float*)d_in[3];
    const float* wu   = (const float*)d_in[4];
    const float* wd   = (const float*)d_in[5];

    float* out        = (float*)d_out;
    float* out_logits = (float*)d_out + (size_t)T_TOKENS * H_DIM;

    cudaFuncSetAttribute(gemm1_kernel, cudaFuncAttributeMaxDynamicSharedMemorySize, G1_SMEM);
    cudaFuncSetAttribute(gemm2_kernel, cudaFuncAttributeMaxDynamicSharedMemorySize, G2_SMEM);

    reset_kernel<<<1, 32>>>();

    int grid = T_TOKENS + 3 * SPLIT_BLOCKS;
    prep_kernel<<<grid, 256>>>(hs, rmsw, rw, wg, wu, wd, out_logits);

    offsets_kernel<<<1, 1>>>();

    dim3 g1(I_DIM / 64, T_TOKENS / 128, N_EXP);   // 22 x 64 x 8
    gemm1_kernel<<<g1, 256, G1_SMEM>>>();

    dim3 g2(H_DIM / 64, T_TOKENS / 128, N_EXP);   // 32 x 64 x 8
    gemm2_kernel<<<g2, 256, G2_SMEM>>>();

    combine_kernel<<<T_TOKENS, 256>>>(out);
}

// round 13
// speedup vs baseline: 2.5898x; 1.0039x over previous
#include <cuda_runtime.h>
#include <cuda_fp16.h>
#include <math.h>
#include <stdint.h>

#define T_TOKENS 8192
#define H_DIM    2048
#define I_DIM    1408
#define N_EXP    8
#define MAXTOK   8192
#define TOTROWS  (2*T_TOKENS)
#define WELEMS   (N_EXP * I_DIM * H_DIM)
#define SPLIT_N4 (WELEMS / 4)
#define SPLIT_BLOCKS ((SPLIT_N4 + 255) / 256)

// ---------------- scratch (static device globals) ----------------
__device__ __half g_xn[(size_t)T_TOKENS*H_DIM];
__device__ __half g_h [(size_t)(TOTROWS+128)*I_DIM];
__device__ int    g_cnt[N_EXP];
__device__ int    g_off[N_EXP];
__device__ int    g_tok[N_EXP*MAXTOK];
__device__ float  g_wt [N_EXP*MAXTOK];
// fp16 weights (single term)
__device__ __half g_wg[(size_t)WELEMS];
__device__ __half g_wu[(size_t)WELEMS];
__device__ __half g_wd[(size_t)WELEMS];

// ---------------- helpers ----------------
__device__ __forceinline__ uint32_t smem_u32(const void* p) {
    uint32_t a;
    asm("{ .reg .u64 t; cvta.to.shared.u64 t, %1; cvt.u32.u64 %0, t; }" : "=r"(a) : "l"(p));
    return a;
}
__device__ __forceinline__ void ldsm_x4(uint32_t* r, uint32_t addr) {
    asm volatile("ldmatrix.sync.aligned.m8n8.x4.shared.b16 {%0,%1,%2,%3}, [%4];"
        : "=r"(r[0]), "=r"(r[1]), "=r"(r[2]), "=r"(r[3]) : "r"(addr));
}
__device__ __forceinline__ void mma_fp16(float* c, const uint32_t* a, const uint32_t* b) {
    asm volatile(
        "mma.sync.aligned.m16n8k16.row.col.f32.f16.f16.f32 "
        "{%0,%1,%2,%3}, {%4,%5,%6,%7}, {%8,%9}, {%0,%1,%2,%3};"
        : "+f"(c[0]), "+f"(c[1]), "+f"(c[2]), "+f"(c[3])
        : "r"(a[0]), "r"(a[1]), "r"(a[2]), "r"(a[3]), "r"(b[0]), "r"(b[1]));
}
__device__ __forceinline__ void cp16(uint32_t dst, const void* src, uint32_t sz) {
    asm volatile("cp.async.cg.shared.global [%0], [%1], 16, %2;"
        :: "r"(dst), "l"(src), "r"(sz) : "memory");
}
#define CP_COMMIT() asm volatile("cp.async.commit_group;" ::: "memory")
template<int N> __device__ __forceinline__ void cp_wait() {
    asm volatile("cp.async.wait_group %0;" :: "n"(N) : "memory");
}
__device__ __forceinline__ uint32_t packh2(__half a, __half b) {
    __half2 v = __halves2half2(a, b);
    return *reinterpret_cast<uint32_t*>(&v);
}
__device__ __forceinline__ float warp_sum(float v) {
#pragma unroll
    for (int o = 16; o > 0; o >>= 1)
        v += __shfl_xor_sync(0xFFFFFFFFu, v, o);
    return v;
}

// ---------------------------------------------------------------------------
__global__ void reset_kernel() {
    if (threadIdx.x < N_EXP) g_cnt[threadIdx.x] = 0;
}

// ---------------------------------------------------------------------------
// Fused prep kernel: router blocks (also zero out rows) + weight-cast blocks.
__global__ __launch_bounds__(256) void prep_kernel(
    const float* __restrict__ hs,
    const float* __restrict__ rmsw,
    const float* __restrict__ rw,
    const float* __restrict__ wg,
    const float* __restrict__ wu,
    const float* __restrict__ wd,
    float* __restrict__ out,
    float* __restrict__ out_logits)
{
    const int tid = threadIdx.x;

    if (blockIdx.x >= T_TOKENS) {
        int sb = blockIdx.x - T_TOKENS;
        int w = sb / SPLIT_BLOCKS;
        int i = (sb - w * SPLIT_BLOCKS) * 256 + tid;
        if (i >= SPLIT_N4) return;
        const float* src = (w == 0) ? wg : (w == 1) ? wu : wd;
        __half* hi = (w == 0) ? g_wg : (w == 1) ? g_wu : g_wd;
        float4 v = ((const float4*)src)[i];
        ((uint2*)hi)[i] = make_uint2(
            packh2(__float2half_rn(v.x), __float2half_rn(v.y)),
            packh2(__float2half_rn(v.z), __float2half_rn(v.w)));
        return;
    }

    const int t    = blockIdx.x;
    const int wid  = tid >> 5;
    const int lane = tid & 31;
    const float* x = hs + (size_t)t * H_DIM;

    // zero this token's output row (gemm2 accumulates atomically)
    {
        float4 z = make_float4(0.f, 0.f, 0.f, 0.f);
        float* orow = out + (size_t)t * H_DIM;
#pragma unroll
        for (int it = 0; it < 2; it++)
            *(float4*)(orow + (tid + it * 256) * 4) = z;
    }

    __shared__ float swred[8];
    __shared__ float sacc[8][N_EXP];
    __shared__ float s_scale;
    __shared__ float slog[N_EXP];

    float ss = 0.f;
    for (int i = tid; i < H_DIM; i += 256) { float v = x[i]; ss += v * v; }
    ss = warp_sum(ss);
    if (lane == 0) swred[wid] = ss;
    __syncthreads();
    if (tid == 0) {
        float tot = 0.f;
#pragma unroll
        for (int w = 0; w < 8; w++) tot += swred[w];
        s_scale = rsqrtf(tot / (float)H_DIM + 1e-6f);
    }
    __syncthreads();
    const float scale = s_scale;

    float acc[N_EXP];
#pragma unroll
    for (int e = 0; e < N_EXP; e++) acc[e] = 0.f;
    for (int i = tid; i < H_DIM; i += 256) {
        float v = x[i] * scale * rmsw[i];
        g_xn[(size_t)t * H_DIM + i] = __float2half_rn(v);
#pragma unroll
        for (int e = 0; e < N_EXP; e++) acc[e] += v * rw[e * H_DIM + i];
    }
#pragma unroll
    for (int e = 0; e < N_EXP; e++) {
        float v = warp_sum(acc[e]);
        if (lane == 0) sacc[wid][e] = v;
    }
    __syncthreads();
    if (tid < N_EXP) {
        float tot = 0.f;
#pragma unroll
        for (int w = 0; w < 8; w++) tot += sacc[w][tid];
        slog[tid] = tot;
    }
    __syncthreads();

    if (tid == 0) {
        float l[N_EXP], m = -1e30f;
#pragma unroll
        for (int e = 0; e < N_EXP; e++) {
            l[e] = slog[e];
            out_logits[(size_t)t * N_EXP + e] = l[e];
            m = fmaxf(m, l[e]);
        }
        float p[N_EXP], s = 0.f;
#pragma unroll
        for (int e = 0; e < N_EXP; e++) { p[e] = expf(l[e] - m); s += p[e]; }
#pragma unroll
        for (int e = 0; e < N_EXP; e++) p[e] /= s;

        int a = 0;
#pragma unroll
        for (int e = 1; e < N_EXP; e++) if (p[e] > p[a]) a = e;
        int b = (a == 0) ? 1 : 0;
#pragma unroll
        for (int e = 0; e < N_EXP; e++) if (e != a && p[e] > p[b]) b = e;

        float wsum = p[a] + p[b] + 1e-20f;
        float wa = p[a] / wsum, wb = p[b] / wsum;

        int pa = atomicAdd(&g_cnt[a], 1);
        g_tok[a * MAXTOK + pa] = t;  g_wt[a * MAXTOK + pa] = wa;
        int pb = atomicAdd(&g_cnt[b], 1);
        g_tok[b * MAXTOK + pb] = t;  g_wt[b * MAXTOK + pb] = wb;
    }
}

// ---------------------------------------------------------------------------
__global__ void offsets_kernel() {
    int run = 0;
    for (int e = 0; e < N_EXP; e++) { g_off[e] = run; run += g_cnt[e]; }
}

// ---------------------------------------------------------------------------
// fp16 HMMA GEMMs, 3-stage cp.async pipeline, one sync per K-tile.
// Block tile 128(M) x 64(N), K-tile 64, 256 threads, warp grid 4x2 (warp 32x32),
// 2 CTAs/SM. LDSM addresses fully precomputed in u32.
#define AS 72
#define G1_STG_E (256*AS)                  // halves per stage = 18432
#define G1_STG_B (G1_STG_E*2)              // 36864 B
#define G1_SMEM  (3*G1_STG_B)              // 110592 B
#define G2_STG_E (192*AS)                  // 13824
#define G2_STG_B (G2_STG_E*2)              // 27648 B
#define G2_SMEM  (3*G2_STG_B)              // 82944 B

__global__ __launch_bounds__(256, 2) void gemm1_kernel()
{
    const int e  = blockIdx.z;
    const int mt = blockIdx.y;
    const int nt = blockIdx.x;
    const int cnt = g_cnt[e];
    if (mt * 128 >= cnt) return;
    const int tid = threadIdx.x;
    const int wid = tid >> 5;
    const int lane = tid & 31;

    extern __shared__ __half sm[];
    __shared__ int stok[128];

    if (tid < 128) {
        int row = mt * 128 + tid;
        stok[tid] = (row < cnt) ? g_tok[e * MAXTOK + row] : -1;
    }
    __syncthreads();

    const size_t wbase = (size_t)e * I_DIM * H_DIM + (size_t)(nt * 64) * H_DIM;
    const __half* wgp = g_wg + wbase;
    const __half* wup = g_wu + wbase;

    const uint32_t smb = smem_u32(sm);

    const __half* aSrc[4]; uint32_t aDst[4], aSz[4];
#pragma unroll
    for (int p = 0; p < 4; p++) {
        int q = tid + p * 256;
        int r = q >> 3, c8 = (q & 7) * 8;
        int tok = stok[r];
        aSz[p]  = tok >= 0 ? 16u : 0u;
        aSrc[p] = g_xn + (size_t)(tok < 0 ? 0 : tok) * H_DIM + c8;
        aDst[p] = smb + (uint32_t)(r * AS + c8) * 2u;
    }
    size_t bOfs[2]; uint32_t bDst[2];
#pragma unroll
    for (int p = 0; p < 2; p++) {
        int q = tid + p * 256;
        int n = q >> 3, c8 = (q & 7) * 8;
        bOfs[p] = (size_t)n * H_DIM + c8;
        bDst[p] = smb + (uint32_t)(n * AS + c8) * 2u;
    }

#define G1_LOAD(S, KK) do {                                                     \
    uint32_t so = (uint32_t)(S) * G1_STG_B;                                     \
    _Pragma("unroll")                                                           \
    for (int p = 0; p < 4; p++)                                                 \
        cp16(aDst[p] + so, aSrc[p] + (KK), aSz[p]);                             \
    _Pragma("unroll")                                                           \
    for (int p = 0; p < 2; p++) {                                               \
        size_t o = bOfs[p] + (KK);                                              \
        cp16(bDst[p] + so + 128*AS*2, wgp + o, 16u);                            \
        cp16(bDst[p] + so + 192*AS*2, wup + o, 16u);                            \
    }                                                                           \
} while (0)

    float cg[2][4][4], cu[2][4][4];
#pragma unroll
    for (int i = 0; i < 2; i++)
#pragma unroll
        for (int j = 0; j < 4; j++)
#pragma unroll
            for (int k = 0; k < 4; k++) { cg[i][j][k] = 0.f; cu[i][j][k] = 0.f; }

    const int wm = wid >> 1;
    const int wn = wid & 1;
    const int lr = lane & 15;
    const int lc = (lane >> 4) * 8;

    const uint32_t aB  = smb + (uint32_t)(((wm*32 + lr) * AS + lc) * 2);
    const uint32_t bgB = smb + (uint32_t)((128*AS + (wn*32 + lr) * AS + lc) * 2);
    const uint32_t buB = bgB + 64*AS*2;

    G1_LOAD(0, 0);
    CP_COMMIT();
    G1_LOAD(1, 64);
    CP_COMMIT();

    const int KT = H_DIM / 64;
    int cur = 0, nxt = 2;
#pragma unroll 3
    for (int kt = 0; kt < KT; kt++) {
        if (kt + 1 < KT) cp_wait<1>(); else cp_wait<0>();
        __syncthreads();
        if (kt + 2 < KT) {
            G1_LOAD(nxt, (kt + 2) * 64);
            CP_COMMIT();
        }

        const uint32_t so = (uint32_t)cur * G1_STG_B;

#pragma unroll
        for (int ks = 0; ks < 4; ks++) {
            uint32_t ah[2][4];
#pragma unroll
            for (int mf = 0; mf < 2; mf++)
                ldsm_x4(ah[mf], aB + so + (uint32_t)((mf*16*AS + ks*16) * 2));
            uint32_t bg[2][4], bu[2][4];
#pragma unroll
            for (int n2 = 0; n2 < 2; n2++) {
                uint32_t fo = (uint32_t)((n2*16*AS + ks*16) * 2);
                ldsm_x4(bg[n2], bgB + so + fo);
                ldsm_x4(bu[n2], buB + so + fo);
            }
#pragma unroll
            for (int mf = 0; mf < 2; mf++)
#pragma unroll
            for (int nf = 0; nf < 4; nf++) {
                int n2 = nf >> 1, nh = nf & 1;
                uint32_t bG[2] = { bg[n2][nh], bg[n2][nh+2] };
                uint32_t bU[2] = { bu[n2][nh], bu[n2][nh+2] };
                mma_fp16(cg[mf][nf], ah[mf], bG);
                mma_fp16(cu[mf][nf], ah[mf], bU);
            }
        }
        cur = (cur == 2) ? 0 : cur + 1;
        nxt = (nxt == 2) ? 0 : nxt + 1;
    }
#undef G1_LOAD

    const int off = g_off[e];
#pragma unroll
    for (int mf = 0; mf < 2; mf++)
#pragma unroll
    for (int nf = 0; nf < 4; nf++) {
        int col = nt*64 + wn*32 + nf*8 + (lane & 3)*2;
#pragma unroll
        for (int half = 0; half < 2; half++) {
            int row = mt*128 + wm*32 + mf*16 + (lane >> 2) + half*8;
            if (row < cnt) {
                float g0 = cg[mf][nf][half*2],   g1 = cg[mf][nf][half*2+1];
                float u0 = cu[mf][nf][half*2],   u1 = cu[mf][nf][half*2+1];
                float h0 = (g0 / (1.f + expf(-g0))) * u0;
                float h1 = (g1 / (1.f + expf(-g1))) * u1;
                size_t base = (size_t)(off + row) * I_DIM + col;
                *(uint32_t*)(g_h + base) = packh2(__float2half_rn(h0), __float2half_rn(h1));
            }
        }
    }
}

// ---------------------------------------------------------------------------
// gemm2: y = He @ Wd^T, fused combine: atomicAdd(out[tok], w * y).
__global__ __launch_bounds__(256, 2) void gemm2_kernel(float* __restrict__ out)
{
    const int e  = blockIdx.z;
    const int mt = blockIdx.y;
    const int nt = blockIdx.x;
    const int cnt = g_cnt[e];
    if (mt * 128 >= cnt) return;
    const int tid = threadIdx.x;
    const int wid = tid >> 5;
    const int lane = tid & 31;
    const int off = g_off[e];

    extern __shared__ __half sm[];
    __shared__ int   stok2[128];
    __shared__ float swt[128];

    if (tid < 128) {
        int row = mt * 128 + tid;
        if (row < cnt) {
            stok2[tid] = g_tok[e * MAXTOK + row];
            swt[tid]   = g_wt [e * MAXTOK + row];
        } else { stok2[tid] = 0; swt[tid] = 0.f; }
    }

    const size_t wbase = (size_t)e * H_DIM * I_DIM + (size_t)(nt * 64) * I_DIM;
    const __half* wdp = g_wd + wbase;

    const uint32_t smb = smem_u32(sm);

    const __half* aSrc[4]; uint32_t aDst[4];
#pragma unroll
    for (int p = 0; p < 4; p++) {
        int q = tid + p * 256;
        int r = q >> 3, c8 = (q & 7) * 8;
        aSrc[p] = g_h + (size_t)(off + mt*128 + r) * I_DIM + c8;
        aDst[p] = smb + (uint32_t)(r * AS + c8) * 2u;
    }
    size_t bOfs[2]; uint32_t bDst[2];
#pragma unroll
    for (int p = 0; p < 2; p++) {
        int q = tid + p * 256;
        int n = q >> 3, c8 = (q & 7) * 8;
        bOfs[p] = (size_t)n * I_DIM + c8;
        bDst[p] = smb + (uint32_t)(n * AS + c8) * 2u;
    }

#define G2_LOAD(S, KK) do {                                                     \
    uint32_t so = (uint32_t)(S) * G2_STG_B;                                     \
    _Pragma("unroll")                                                           \
    for (int p = 0; p < 4; p++)                                                 \
        cp16(aDst[p] + so, aSrc[p] + (KK), 16u);                                \
    _Pragma("unroll")                                                           \
    for (int p = 0; p < 2; p++)                                                 \
        cp16(bDst[p] + so + 128*AS*2, wdp + bOfs[p] + (KK), 16u);               \
} while (0)

    float cc[2][4][4];
#pragma unroll
    for (int i = 0; i < 2; i++)
#pragma unroll
        for (int j = 0; j < 4; j++)
#pragma unroll
            for (int k = 0; k < 4; k++) cc[i][j][k] = 0.f;

    const int wm = wid >> 1;
    const int wn = wid & 1;
    const int lr = lane & 15;
    const int lc = (lane >> 4) * 8;

    const uint32_t aB  = smb + (uint32_t)(((wm*32 + lr) * AS + lc) * 2);
    const uint32_t bdB = smb + (uint32_t)((128*AS + (wn*32 + lr) * AS + lc) * 2);

    G2_LOAD(0, 0);
    CP_COMMIT();
    G2_LOAD(1, 64);
    CP_COMMIT();

    const int KT = I_DIM / 64;
    int cur = 0, nxt = 2;
#pragma unroll 3
    for (int kt = 0; kt < KT; kt++) {
        if (kt + 1 < KT) cp_wait<1>(); else cp_wait<0>();
        __syncthreads();
        if (kt + 2 < KT) {
            G2_LOAD(nxt, (kt + 2) * 64);
            CP_COMMIT();
        }

        const uint32_t so = (uint32_t)cur * G2_STG_B;

#pragma unroll
        for (int ks = 0; ks < 4; ks++) {
            uint32_t ah[2][4];
#pragma unroll
            for (int mf = 0; mf < 2; mf++)
                ldsm_x4(ah[mf], aB + so + (uint32_t)((mf*16*AS + ks*16) * 2));
            uint32_t bd[2][4];
#pragma unroll
            for (int n2 = 0; n2 < 2; n2++)
                ldsm_x4(bd[n2], bdB + so + (uint32_t)((n2*16*AS + ks*16) * 2));
#pragma unroll
            for (int mf = 0; mf < 2; mf++)
#pragma unroll
            for (int nf = 0; nf < 4; nf++) {
                int n2 = nf >> 1, nh = nf & 1;
                uint32_t bB[2] = { bd[n2][nh], bd[n2][nh+2] };
                mma_fp16(cc[mf][nf], ah[mf], bB);
            }
        }
        cur = (cur == 2) ? 0 : cur + 1;
        nxt = (nxt == 2) ? 0 : nxt + 1;
    }
#undef G2_LOAD

    // fused combine epilogue: out[tok] += w * y (exact-commutative fp32 adds)
#pragma unroll
    for (int mf = 0; mf < 2; mf++)
#pragma unroll
    for (int nf = 0; nf < 4; nf++) {
        int col = nt*64 + wn*32 + nf*8 + (lane & 3)*2;
#pragma unroll
        for (int half = 0; half < 2; half++) {
            int mloc = wm*32 + mf*16 + (lane >> 2) + half*8;
            int row = mt*128 + mloc;
            if (row < cnt) {
                int tok = stok2[mloc];
                float w = swt[mloc];
                float* o = out + (size_t)tok * H_DIM + col;
                atomicAdd(o,     w * cc[mf][nf][half*2]);
                atomicAdd(o + 1, w * cc[mf][nf][half*2+1]);
            }
        }
    }
}

// ---------------------------------------------------------------------------
extern "C" void kernel_launch(void* const* d_in, const int* in_sizes, int n_in,
                              void* d_out, int out_size)
{
    const float* hs   = (const float*)d_in[0];
    const float* rmsw = (const float*)d_in[1];
    const float* rw   = (const float*)d_in[2];
    const float* wg   = (const float*)d_in[3];
    const float* wu   = (const float*)d_in[4];
    const float* wd   = (const float*)d_in[5];

    float* out        = (float*)d_out;
    float* out_logits = (float*)d_out + (size_t)T_TOKENS * H_DIM;

    cudaFuncSetAttribute(gemm1_kernel, cudaFuncAttributeMaxDynamicSharedMemorySize, G1_SMEM);
    cudaFuncSetAttribute(gemm2_kernel, cudaFuncAttributeMaxDynamicSharedMemorySize, G2_SMEM);

    reset_kernel<<<1, 32>>>();

    int grid = T_TOKENS + 3 * SPLIT_BLOCKS;
    prep_kernel<<<grid, 256>>>(hs, rmsw, rw, wg, wu, wd, out, out_logits);

    offsets_kernel<<<1, 1>>>();

    dim3 g1(I_DIM / 64, T_TOKENS / 128, N_EXP);   // 22 x 64 x 8
    gemm1_kernel<<<g1, 256, G1_SMEM>>>();

    dim3 g2(H_DIM / 64, T_TOKENS / 128, N_EXP);   // 32 x 64 x 8
    gemm2_kernel<<<g2, 256, G2_SMEM>>>(out);
}